// round 1
// baseline (speedup 1.0000x reference)
#include <cuda_runtime.h>
#include <cuda_bf16.h>
#include <math_constants.h>

// Problem constants
#define BATCH 4
#define SEQ   2048
#define EMBD  1024
#define NHEAD 16
#define HDIM  64
#define QKV3  (3 * EMBD)
#define MTOK  (BATCH * SEQ)   // 8192 rows

// Scratch (allowed: __device__ globals, no runtime allocation)
__device__ float g_qkv[(size_t)MTOK * QKV3];   // [B*T, 3C]
__device__ float g_att[(size_t)MTOK * EMBD];   // [B*T, C] attention output

// ---------------------------------------------------------------------------
// SGEMM: C[M,N] = A[M,K] @ B[K,N] + bias[N]
// 128x128 block tile, BK=16, 256 threads, 8x8 per-thread micro-tile.
// ---------------------------------------------------------------------------
#define BM 128
#define BN 128
#define BK 16
#define TM 8
#define TN 8

__device__ __forceinline__ void sgemm_body(
    const float* __restrict__ A, const float* __restrict__ Bm,
    const float* __restrict__ bias, float* __restrict__ C,
    int M, int N, int K)
{
    __shared__ float As[BK][BM];   // transposed A tile
    __shared__ float Bs[BK][BN];

    const int tid = threadIdx.x;
    const int bx = blockIdx.x, by = blockIdx.y;
    const int tx = tid & 15, ty = tid >> 4;
    const int row0 = by * BM, col0 = bx * BN;

    float acc[TM][TN];
#pragma unroll
    for (int i = 0; i < TM; i++)
#pragma unroll
        for (int j = 0; j < TN; j++) acc[i][j] = 0.f;

    for (int kt = 0; kt < K; kt += BK) {
        // Load A tile: BM x BK = 512 float4, 2 per thread, store transposed
#pragma unroll
        for (int l = 0; l < 2; l++) {
            int id = tid + l * 256;
            int r = id >> 2;            // BK/4 = 4 float4 per row
            int c = (id & 3) * 4;
            float4 v = *reinterpret_cast<const float4*>(
                &A[(size_t)(row0 + r) * K + kt + c]);
            As[c + 0][r] = v.x; As[c + 1][r] = v.y;
            As[c + 2][r] = v.z; As[c + 3][r] = v.w;
        }
        // Load B tile: BK x BN = 512 float4, 2 per thread
#pragma unroll
        for (int l = 0; l < 2; l++) {
            int id = tid + l * 256;
            int r = id >> 5;            // BN/4 = 32 float4 per row
            int c = (id & 31) * 4;
            *reinterpret_cast<float4*>(&Bs[r][c]) =
                *reinterpret_cast<const float4*>(
                    &Bm[(size_t)(kt + r) * N + col0 + c]);
        }
        __syncthreads();

#pragma unroll
        for (int k = 0; k < BK; k++) {
            float a[TM], b[TN];
#pragma unroll
            for (int i = 0; i < TM; i++) a[i] = As[k][ty * TM + i];
#pragma unroll
            for (int j = 0; j < TN; j++) b[j] = Bs[k][tx * TN + j];
#pragma unroll
            for (int i = 0; i < TM; i++)
#pragma unroll
                for (int j = 0; j < TN; j++)
                    acc[i][j] += a[i] * b[j];
        }
        __syncthreads();
    }

#pragma unroll
    for (int i = 0; i < TM; i++) {
        int r = row0 + ty * TM + i;
#pragma unroll
        for (int j = 0; j < TN; j += 4) {
            int cidx = col0 + tx * TN + j;
            float4 v;
            v.x = acc[i][j + 0] + bias[cidx + 0];
            v.y = acc[i][j + 1] + bias[cidx + 1];
            v.z = acc[i][j + 2] + bias[cidx + 2];
            v.w = acc[i][j + 3] + bias[cidx + 3];
            *reinterpret_cast<float4*>(&C[(size_t)r * N + cidx]) = v;
        }
    }
}

__global__ __launch_bounds__(256) void qkv_gemm_kernel(
    const float* __restrict__ x, const float* __restrict__ w,
    const float* __restrict__ bias)
{
    sgemm_body(x, w, bias, g_qkv, MTOK, QKV3, EMBD);
}

__global__ __launch_bounds__(256) void proj_gemm_kernel(
    const float* __restrict__ w, const float* __restrict__ bias,
    float* __restrict__ out)
{
    sgemm_body(g_att, w, bias, out, MTOK, EMBD, EMBD);
}

// ---------------------------------------------------------------------------
// Flash attention (fp32, causal). One block per (q-tile of 64, head, batch).
// 256 threads: 4 threads per q-row; each thread owns 8 S columns per k-tile
// and 16 (strided) D columns of the output accumulator.
// ---------------------------------------------------------------------------
#define TQ 64
#define TKT 32

__global__ __launch_bounds__(256) void flash_attn_kernel(
    float* __restrict__ out)
{
    __shared__ float q_s[TQ][HDIM + 1];
    __shared__ float k_s[TKT][HDIM + 1];
    __shared__ float v_s[TKT][HDIM + 1];
    __shared__ float p_s[TQ][TKT + 1];

    const float* __restrict__ qkv = g_qkv;
    const int tid = threadIdx.x;
    const int qt = blockIdx.x, h = blockIdx.y, b = blockIdx.z;
    const int row = tid >> 2, sub = tid & 3;
    const int stride = QKV3;
    const int qidx = qt * TQ + row;
    const float scale = 0.125f;   // 1/sqrt(64)

    // Load Q tile: 64x64 floats = 1024 float4, 4 per thread
#pragma unroll
    for (int l = 0; l < 4; l++) {
        int id = tid + l * 256;
        int r = id >> 4;            // 16 float4 per row
        int c = (id & 15) * 4;
        float4 v = *reinterpret_cast<const float4*>(
            &qkv[(size_t)(b * SEQ + qt * TQ + r) * stride + h * HDIM + c]);
        q_s[r][c] = v.x; q_s[r][c + 1] = v.y;
        q_s[r][c + 2] = v.z; q_s[r][c + 3] = v.w;
    }

    float m = -CUDART_INF_F, lsum = 0.f;
    float acc[16];
#pragma unroll
    for (int i = 0; i < 16; i++) acc[i] = 0.f;

    const int nkt = 2 * qt + 2;   // causal: skip fully-masked k-tiles
    for (int kt = 0; kt < nkt; kt++) {
        __syncthreads();   // previous iteration's smem reads done
        // Load K and V tiles: 32x64 each = 512 float4, 2 per thread each
#pragma unroll
        for (int l = 0; l < 2; l++) {
            int id = tid + l * 256;
            int r = id >> 4;
            int c = (id & 15) * 4;
            size_t g = (size_t)(b * SEQ + kt * TKT + r) * stride + EMBD + h * HDIM + c;
            float4 kv = *reinterpret_cast<const float4*>(&qkv[g]);
            k_s[r][c] = kv.x; k_s[r][c + 1] = kv.y;
            k_s[r][c + 2] = kv.z; k_s[r][c + 3] = kv.w;
            float4 vv = *reinterpret_cast<const float4*>(&qkv[g + EMBD]);
            v_s[r][c] = vv.x; v_s[r][c + 1] = vv.y;
            v_s[r][c + 2] = vv.z; v_s[r][c + 3] = vv.w;
        }
        __syncthreads();

        // S = Q K^T for this thread's 8 columns
        float s[8];
#pragma unroll
        for (int j = 0; j < 8; j++) s[j] = 0.f;
#pragma unroll
        for (int d = 0; d < HDIM; d++) {
            float qv = q_s[row][d];
#pragma unroll
            for (int j = 0; j < 8; j++)
                s[j] += qv * k_s[sub * 8 + j][d];
        }

        // causal mask + scale + row max
        float smax = -CUDART_INF_F;
#pragma unroll
        for (int j = 0; j < 8; j++) {
            int kidx = kt * TKT + sub * 8 + j;
            s[j] = (kidx <= qidx) ? s[j] * scale : -CUDART_INF_F;
            smax = fmaxf(smax, s[j]);
        }
        smax = fmaxf(smax, __shfl_xor_sync(0xffffffffu, smax, 1));
        smax = fmaxf(smax, __shfl_xor_sync(0xffffffffu, smax, 2));

        float m_new = fmaxf(m, smax);
        float corr = __expf(m - m_new);   // exp(-inf - finite) = 0 on first tile

        float psum = 0.f;
#pragma unroll
        for (int j = 0; j < 8; j++) {
            float p = __expf(s[j] - m_new);
            p_s[row][sub * 8 + j] = p;
            psum += p;
        }
        psum += __shfl_xor_sync(0xffffffffu, psum, 1);
        psum += __shfl_xor_sync(0xffffffffu, psum, 2);
        lsum = lsum * corr + psum;
        m = m_new;

#pragma unroll
        for (int i = 0; i < 16; i++) acc[i] *= corr;

        __syncwarp();   // p_s row written & read within the same warp

        // O += P @ V  (this thread's 16 strided D columns: d = sub + 4*i)
#pragma unroll
        for (int j = 0; j < TKT; j++) {
            float p = p_s[row][j];
#pragma unroll
            for (int i = 0; i < 16; i++)
                acc[i] += p * v_s[j][sub + 4 * i];
        }
    }

    float inv = 1.f / lsum;
    size_t obase = (size_t)(b * SEQ + qidx) * EMBD + h * HDIM;
#pragma unroll
    for (int i = 0; i < 16; i++)
        g_att[obase + sub + 4 * i] = acc[i] * inv;
}

// ---------------------------------------------------------------------------
// Launch
// ---------------------------------------------------------------------------
extern "C" void kernel_launch(void* const* d_in, const int* in_sizes, int n_in,
                              void* d_out, int out_size)
{
    const float* x      = (const float*)d_in[0];
    const float* w_attn = (const float*)d_in[1];
    const float* b_attn = (const float*)d_in[2];
    const float* w_proj = (const float*)d_in[3];
    const float* b_proj = (const float*)d_in[4];
    float* out = (float*)d_out;

    // QKV: [8192,1024] @ [1024,3072] + b -> g_qkv
    dim3 g1(QKV3 / BN, MTOK / BM);
    qkv_gemm_kernel<<<g1, 256>>>(x, w_attn, b_attn);

    // Flash attention: g_qkv -> g_att ([B,T,C] layout directly)
    dim3 g2(SEQ / TQ, NHEAD, BATCH);
    flash_attn_kernel<<<g2, 256>>>(nullptr == nullptr ? (float*)0 : (float*)0);

    // Proj: g_att @ [1024,1024] + b -> out
    dim3 g3(EMBD / BN, MTOK / BM);
    proj_gemm_kernel<<<g3, 256>>>(w_proj, b_proj, out);
}

// round 2
// speedup vs baseline: 1.3145x; 1.3145x over previous
#include <cuda_runtime.h>
#include <cuda_bf16.h>
#include <math_constants.h>
#include <cstdint>

// Problem constants
#define BATCH 4
#define SEQ   2048
#define EMBD  1024
#define NHEAD 16
#define HDIM  64
#define QKV3  (3 * EMBD)
#define MTOK  (BATCH * SEQ)   // 8192 rows

// Scratch (__device__ globals: allowed)
__device__ float g_qkv[(size_t)MTOK * QKV3];   // [B*T, 3C]
__device__ float g_att[(size_t)MTOK * EMBD];   // [B*T, C]

// ---------------------------------------------------------------------------
// TF32 helpers
// ---------------------------------------------------------------------------
__device__ __forceinline__ float f2tf(float x) {
    uint32_t u;
    asm("cvt.rna.tf32.f32 %0, %1;" : "=r"(u) : "f"(x));
    return __uint_as_float(u);
}

__device__ __forceinline__ void mma_tf32(float c[4], const uint32_t a[4],
                                         const uint32_t b[2]) {
    asm volatile(
        "mma.sync.aligned.m16n8k8.row.col.f32.tf32.tf32.f32 "
        "{%0,%1,%2,%3}, {%4,%5,%6,%7}, {%8,%9}, {%0,%1,%2,%3};"
        : "+f"(c[0]), "+f"(c[1]), "+f"(c[2]), "+f"(c[3])
        : "r"(a[0]), "r"(a[1]), "r"(a[2]), "r"(a[3]), "r"(b[0]), "r"(b[1]));
}

// ---------------------------------------------------------------------------
// TF32 MMA GEMM: C[M,N] = A[M,K] @ B[K,N] + bias
// 128x128x16 CTA tile, 256 threads = 8 warps in 4(m) x 2(n); warp = 32x64.
// ---------------------------------------------------------------------------
#define BM 128
#define BN 128
#define BK 16
#define GPAD 8   // (128+8) mod 32 == 8 -> frag loads bank-conflict-free

__device__ __forceinline__ void gemm_body(
    const float* __restrict__ A, const float* __restrict__ Bm,
    const float* __restrict__ bias, float* __restrict__ C,
    int M, int N, int K)
{
    __shared__ float As[BK][BM + GPAD];   // [k][m]
    __shared__ float Bs[BK][BN + GPAD];   // [k][n]

    const int tid = threadIdx.x, wid = tid >> 5, lane = tid & 31;
    const int g = lane >> 2, tg = lane & 3;
    const int wm = wid & 3, wn = wid >> 2;
    const int row0 = blockIdx.y * BM, col0 = blockIdx.x * BN;

    float c[2][8][4];
#pragma unroll
    for (int mf = 0; mf < 2; mf++)
#pragma unroll
        for (int nf = 0; nf < 8; nf++)
#pragma unroll
            for (int i = 0; i < 4; i++) c[mf][nf][i] = 0.f;

    for (int kt = 0; kt < K; kt += BK) {
        // A tile 128x16 -> transposed As[k][m], tf32-rounded
#pragma unroll
        for (int l = 0; l < 2; l++) {
            int id = tid + l * 256;
            int r = id >> 2, cc = (id & 3) * 4;
            float4 v = *reinterpret_cast<const float4*>(
                &A[(size_t)(row0 + r) * K + kt + cc]);
            As[cc + 0][r] = f2tf(v.x); As[cc + 1][r] = f2tf(v.y);
            As[cc + 2][r] = f2tf(v.z); As[cc + 3][r] = f2tf(v.w);
        }
        // B tile 16x128 -> Bs[k][n], tf32-rounded
#pragma unroll
        for (int l = 0; l < 2; l++) {
            int id = tid + l * 256;
            int r = id >> 5, cc = (id & 31) * 4;
            float4 v = *reinterpret_cast<const float4*>(
                &Bm[(size_t)(kt + r) * N + col0 + cc]);
            Bs[r][cc + 0] = f2tf(v.x); Bs[r][cc + 1] = f2tf(v.y);
            Bs[r][cc + 2] = f2tf(v.z); Bs[r][cc + 3] = f2tf(v.w);
        }
        __syncthreads();

#pragma unroll
        for (int ks = 0; ks < BK; ks += 8) {
            uint32_t a[2][4], b[8][2];
#pragma unroll
            for (int mf = 0; mf < 2; mf++) {
                int m0 = wm * 32 + mf * 16;
                a[mf][0] = __float_as_uint(As[ks + tg][m0 + g]);
                a[mf][1] = __float_as_uint(As[ks + tg][m0 + g + 8]);
                a[mf][2] = __float_as_uint(As[ks + tg + 4][m0 + g]);
                a[mf][3] = __float_as_uint(As[ks + tg + 4][m0 + g + 8]);
            }
#pragma unroll
            for (int nf = 0; nf < 8; nf++) {
                int n0 = wn * 64 + nf * 8;
                b[nf][0] = __float_as_uint(Bs[ks + tg][n0 + g]);
                b[nf][1] = __float_as_uint(Bs[ks + tg + 4][n0 + g]);
            }
#pragma unroll
            for (int mf = 0; mf < 2; mf++)
#pragma unroll
                for (int nf = 0; nf < 8; nf++)
                    mma_tf32(c[mf][nf], a[mf], b[nf]);
        }
        __syncthreads();
    }

    // Epilogue: C frag (c0,c1)@(g, 2tg), (c2,c3)@(g+8, 2tg)
#pragma unroll
    for (int mf = 0; mf < 2; mf++) {
        int r_lo = row0 + wm * 32 + mf * 16 + g;
#pragma unroll
        for (int nf = 0; nf < 8; nf++) {
            int cc = col0 + wn * 64 + nf * 8 + tg * 2;
            float b0 = bias[cc], b1 = bias[cc + 1];
            float2 v0 = make_float2(c[mf][nf][0] + b0, c[mf][nf][1] + b1);
            float2 v1 = make_float2(c[mf][nf][2] + b0, c[mf][nf][3] + b1);
            *reinterpret_cast<float2*>(&C[(size_t)r_lo * N + cc]) = v0;
            *reinterpret_cast<float2*>(&C[(size_t)(r_lo + 8) * N + cc]) = v1;
        }
    }
}

__global__ __launch_bounds__(256) void qkv_gemm_kernel(
    const float* __restrict__ x, const float* __restrict__ w,
    const float* __restrict__ bias)
{
    gemm_body(x, w, bias, g_qkv, MTOK, QKV3, EMBD);
}

__global__ __launch_bounds__(256) void proj_gemm_kernel(
    const float* __restrict__ w, const float* __restrict__ bias,
    float* __restrict__ out)
{
    gemm_body(g_att, w, bias, out, MTOK, EMBD, EMBD);
}

// ---------------------------------------------------------------------------
// Flash attention (fp32, causal), LDS-optimized.
// Block = (q-tile 64, head, batch), 256 threads, 4 threads (subs) per q-row.
// K stored transposed in smem so QK reads float4 of K; O accumulator mapped
// d = i*16 + sub*4 so PV reads float4 of V, conflict-free.
// ---------------------------------------------------------------------------
#define TQ 64
#define TKT 32

__global__ __launch_bounds__(256) void flash_attn_kernel()
{
    __shared__ float q_s [TQ][HDIM + 4];    // stride 68 floats (16B aligned)
    __shared__ float kt_s[HDIM][TKT + 4];   // K transposed: [d][token], stride 36
    __shared__ float v_s [TKT][HDIM + 4];
    __shared__ float p_s [TQ][TKT + 1];

    const float* __restrict__ qkv = g_qkv;
    const int tid = threadIdx.x;
    const int qt = blockIdx.x, h = blockIdx.y, b = blockIdx.z;
    const int row = tid >> 2, sub = tid & 3;
    const int qidx = qt * TQ + row;
    const float scale = 0.125f;   // 1/sqrt(64)

    // Q tile 64x64: 1024 float4, 4 per thread
#pragma unroll
    for (int l = 0; l < 4; l++) {
        int id = tid + l * 256;
        int r = id >> 4, cc = (id & 15) * 4;
        float4 v = *reinterpret_cast<const float4*>(
            &qkv[(size_t)(b * SEQ + qt * TQ + r) * QKV3 + h * HDIM + cc]);
        *reinterpret_cast<float4*>(&q_s[r][cc]) = v;
    }

    float m = -CUDART_INF_F, lsum = 0.f;
    float4 acc[4];
#pragma unroll
    for (int i = 0; i < 4; i++) acc[i] = make_float4(0.f, 0.f, 0.f, 0.f);

    const int nkt = 2 * qt + 2;   // causal: skip fully-masked k-tiles
    for (int kt = 0; kt < nkt; kt++) {
        __syncthreads();
        // K (transposed) + V tiles: 32x64 each, 2 float4 per thread each
#pragma unroll
        for (int l = 0; l < 2; l++) {
            int id = tid + l * 256;
            int r = id >> 4, cc = (id & 15) * 4;
            size_t gaddr = (size_t)(b * SEQ + kt * TKT + r) * QKV3
                           + EMBD + h * HDIM + cc;
            float4 kv = *reinterpret_cast<const float4*>(&qkv[gaddr]);
            kt_s[cc + 0][r] = kv.x; kt_s[cc + 1][r] = kv.y;
            kt_s[cc + 2][r] = kv.z; kt_s[cc + 3][r] = kv.w;
            float4 vv = *reinterpret_cast<const float4*>(&qkv[gaddr + EMBD]);
            *reinterpret_cast<float4*>(&v_s[r][cc]) = vv;
        }
        __syncthreads();

        // S = Q K^T: thread owns k-columns sub*8 .. sub*8+7
        float s[8];
#pragma unroll
        for (int j = 0; j < 8; j++) s[j] = 0.f;
#pragma unroll
        for (int d = 0; d < HDIM; d++) {
            float qv = q_s[row][d];
            float4 k0 = *reinterpret_cast<const float4*>(&kt_s[d][sub * 8]);
            float4 k1 = *reinterpret_cast<const float4*>(&kt_s[d][sub * 8 + 4]);
            s[0] += qv * k0.x; s[1] += qv * k0.y;
            s[2] += qv * k0.z; s[3] += qv * k0.w;
            s[4] += qv * k1.x; s[5] += qv * k1.y;
            s[6] += qv * k1.z; s[7] += qv * k1.w;
        }

        // mask + scale + online softmax
        float smax = -CUDART_INF_F;
#pragma unroll
        for (int j = 0; j < 8; j++) {
            int kidx = kt * TKT + sub * 8 + j;
            s[j] = (kidx <= qidx) ? s[j] * scale : -CUDART_INF_F;
            smax = fmaxf(smax, s[j]);
        }
        smax = fmaxf(smax, __shfl_xor_sync(0xffffffffu, smax, 1));
        smax = fmaxf(smax, __shfl_xor_sync(0xffffffffu, smax, 2));

        float m_new = fmaxf(m, smax);
        float corr = __expf(m - m_new);

        float psum = 0.f;
#pragma unroll
        for (int j = 0; j < 8; j++) {
            float p = __expf(s[j] - m_new);
            p_s[row][sub * 8 + j] = p;
            psum += p;
        }
        psum += __shfl_xor_sync(0xffffffffu, psum, 1);
        psum += __shfl_xor_sync(0xffffffffu, psum, 2);
        lsum = lsum * corr + psum;
        m = m_new;

#pragma unroll
        for (int i = 0; i < 4; i++) {
            acc[i].x *= corr; acc[i].y *= corr;
            acc[i].z *= corr; acc[i].w *= corr;
        }

        __syncwarp();   // p_s row written/read within same warp

        // O += P @ V : thread owns d = i*16 + sub*4 + {0..3}, i = 0..3
#pragma unroll
        for (int j = 0; j < TKT; j++) {
            float p = p_s[row][j];
#pragma unroll
            for (int i = 0; i < 4; i++) {
                float4 v4 = *reinterpret_cast<const float4*>(
                    &v_s[j][i * 16 + sub * 4]);
                acc[i].x += p * v4.x; acc[i].y += p * v4.y;
                acc[i].z += p * v4.z; acc[i].w += p * v4.w;
            }
        }
    }

    float inv = 1.f / lsum;
    size_t ob = (size_t)(b * SEQ + qidx) * EMBD + h * HDIM;
#pragma unroll
    for (int i = 0; i < 4; i++) {
        float4 o = make_float4(acc[i].x * inv, acc[i].y * inv,
                               acc[i].z * inv, acc[i].w * inv);
        *reinterpret_cast<float4*>(&g_att[ob + i * 16 + sub * 4]) = o;
    }
}

// ---------------------------------------------------------------------------
// Launch
// ---------------------------------------------------------------------------
extern "C" void kernel_launch(void* const* d_in, const int* in_sizes, int n_in,
                              void* d_out, int out_size)
{
    const float* x      = (const float*)d_in[0];
    const float* w_attn = (const float*)d_in[1];
    const float* b_attn = (const float*)d_in[2];
    const float* w_proj = (const float*)d_in[3];
    const float* b_proj = (const float*)d_in[4];
    float* out = (float*)d_out;

    dim3 g1(QKV3 / BN, MTOK / BM);
    qkv_gemm_kernel<<<g1, 256>>>(x, w_attn, b_attn);

    dim3 g2(SEQ / TQ, NHEAD, BATCH);
    flash_attn_kernel<<<g2, 256>>>();

    dim3 g3(EMBD / BN, MTOK / BM);
    proj_gemm_kernel<<<g3, 256>>>(w_proj, b_proj, out);
}

// round 3
// speedup vs baseline: 3.5901x; 2.7311x over previous
#include <cuda_runtime.h>
#include <cuda_bf16.h>
#include <math_constants.h>
#include <cstdint>

// Problem constants
#define BATCH 4
#define SEQ   2048
#define EMBD  1024
#define NHEAD 16
#define HDIM  64
#define QKV3  (3 * EMBD)
#define MTOK  (BATCH * SEQ)   // 8192 rows

// Scratch (__device__ globals: allowed)
__device__ float g_qkv[(size_t)MTOK * QKV3];   // [B*T, 3C]
__device__ float g_att[(size_t)MTOK * EMBD];   // [B*T, C]

// ---------------------------------------------------------------------------
// TF32 helpers
// ---------------------------------------------------------------------------
__device__ __forceinline__ float f2tf(float x) {
    uint32_t u;
    asm("cvt.rna.tf32.f32 %0, %1;" : "=r"(u) : "f"(x));
    return __uint_as_float(u);
}

__device__ __forceinline__ void mma_tf32(float c[4], const uint32_t a[4],
                                         const uint32_t b[2]) {
    asm volatile(
        "mma.sync.aligned.m16n8k8.row.col.f32.tf32.tf32.f32 "
        "{%0,%1,%2,%3}, {%4,%5,%6,%7}, {%8,%9}, {%0,%1,%2,%3};"
        : "+f"(c[0]), "+f"(c[1]), "+f"(c[2]), "+f"(c[3])
        : "r"(a[0]), "r"(a[1]), "r"(a[2]), "r"(a[3]), "r"(b[0]), "r"(b[1]));
}

// ---------------------------------------------------------------------------
// TF32 MMA GEMM: C[M,N] = A[M,K] @ B[K,N] + bias (unchanged from round 2)
// ---------------------------------------------------------------------------
#define BM 128
#define BN 128
#define BK 16
#define GPAD 8

__device__ __forceinline__ void gemm_body(
    const float* __restrict__ A, const float* __restrict__ Bm,
    const float* __restrict__ bias, float* __restrict__ C,
    int M, int N, int K)
{
    __shared__ float As[BK][BM + GPAD];
    __shared__ float Bs[BK][BN + GPAD];

    const int tid = threadIdx.x, wid = tid >> 5, lane = tid & 31;
    const int g = lane >> 2, tg = lane & 3;
    const int wm = wid & 3, wn = wid >> 2;
    const int row0 = blockIdx.y * BM, col0 = blockIdx.x * BN;

    float c[2][8][4];
#pragma unroll
    for (int mf = 0; mf < 2; mf++)
#pragma unroll
        for (int nf = 0; nf < 8; nf++)
#pragma unroll
            for (int i = 0; i < 4; i++) c[mf][nf][i] = 0.f;

    for (int kt = 0; kt < K; kt += BK) {
#pragma unroll
        for (int l = 0; l < 2; l++) {
            int id = tid + l * 256;
            int r = id >> 2, cc = (id & 3) * 4;
            float4 v = *reinterpret_cast<const float4*>(
                &A[(size_t)(row0 + r) * K + kt + cc]);
            As[cc + 0][r] = f2tf(v.x); As[cc + 1][r] = f2tf(v.y);
            As[cc + 2][r] = f2tf(v.z); As[cc + 3][r] = f2tf(v.w);
        }
#pragma unroll
        for (int l = 0; l < 2; l++) {
            int id = tid + l * 256;
            int r = id >> 5, cc = (id & 31) * 4;
            float4 v = *reinterpret_cast<const float4*>(
                &Bm[(size_t)(kt + r) * N + col0 + cc]);
            Bs[r][cc + 0] = f2tf(v.x); Bs[r][cc + 1] = f2tf(v.y);
            Bs[r][cc + 2] = f2tf(v.z); Bs[r][cc + 3] = f2tf(v.w);
        }
        __syncthreads();

#pragma unroll
        for (int ks = 0; ks < BK; ks += 8) {
            uint32_t a[2][4], b[8][2];
#pragma unroll
            for (int mf = 0; mf < 2; mf++) {
                int m0 = wm * 32 + mf * 16;
                a[mf][0] = __float_as_uint(As[ks + tg][m0 + g]);
                a[mf][1] = __float_as_uint(As[ks + tg][m0 + g + 8]);
                a[mf][2] = __float_as_uint(As[ks + tg + 4][m0 + g]);
                a[mf][3] = __float_as_uint(As[ks + tg + 4][m0 + g + 8]);
            }
#pragma unroll
            for (int nf = 0; nf < 8; nf++) {
                int n0 = wn * 64 + nf * 8;
                b[nf][0] = __float_as_uint(Bs[ks + tg][n0 + g]);
                b[nf][1] = __float_as_uint(Bs[ks + tg + 4][n0 + g]);
            }
#pragma unroll
            for (int mf = 0; mf < 2; mf++)
#pragma unroll
                for (int nf = 0; nf < 8; nf++)
                    mma_tf32(c[mf][nf], a[mf], b[nf]);
        }
        __syncthreads();
    }

#pragma unroll
    for (int mf = 0; mf < 2; mf++) {
        int r_lo = row0 + wm * 32 + mf * 16 + g;
#pragma unroll
        for (int nf = 0; nf < 8; nf++) {
            int cc = col0 + wn * 64 + nf * 8 + tg * 2;
            float b0 = bias[cc], b1 = bias[cc + 1];
            float2 v0 = make_float2(c[mf][nf][0] + b0, c[mf][nf][1] + b1);
            float2 v1 = make_float2(c[mf][nf][2] + b0, c[mf][nf][3] + b1);
            *reinterpret_cast<float2*>(&C[(size_t)r_lo * N + cc]) = v0;
            *reinterpret_cast<float2*>(&C[(size_t)(r_lo + 8) * N + cc]) = v1;
        }
    }
}

__global__ __launch_bounds__(256) void qkv_gemm_kernel(
    const float* __restrict__ x, const float* __restrict__ w,
    const float* __restrict__ bias)
{
    gemm_body(x, w, bias, g_qkv, MTOK, QKV3, EMBD);
}

__global__ __launch_bounds__(256) void proj_gemm_kernel(
    const float* __restrict__ w, const float* __restrict__ bias,
    float* __restrict__ out)
{
    gemm_body(g_att, w, bias, out, MTOK, EMBD, EMBD);
}

// ---------------------------------------------------------------------------
// Tensor-core flash attention (causal).
// Block = (64 q-rows, head, batch), 128 threads = 4 warps, warp owns 16 rows.
// QK^T via tf32x3 (fp32-accurate scores), PV via single tf32.
// ---------------------------------------------------------------------------
#define AQS 68   // Q/K smem stride (floats): frag loads bank-conflict-free
#define AVS 72   // V smem stride: b-frag loads bank-conflict-free
#define APS 68   // P smem stride

#define OFF_QB 0
#define OFF_QS (OFF_QB + 64 * AQS)
#define OFF_KB (OFF_QS + 64 * AQS)
#define OFF_KS (OFF_KB + 64 * AQS)
#define OFF_V  (OFF_KS + 64 * AQS)
#define OFF_P  (OFF_V  + 64 * AVS)
#define ATT_SMEM_FLOATS (OFF_P + 4 * 16 * APS)
#define ATT_SMEM_BYTES  (ATT_SMEM_FLOATS * 4)

__device__ __forceinline__ float4 f2tf4(float4 v) {
    return make_float4(f2tf(v.x), f2tf(v.y), f2tf(v.z), f2tf(v.w));
}

__global__ __launch_bounds__(128) void flash_attn_kernel()
{
    extern __shared__ float smn[];
    float* qb = smn + OFF_QB;
    float* qs = smn + OFF_QS;
    float* kb = smn + OFF_KB;
    float* ks = smn + OFF_KS;
    float* vs = smn + OFF_V;

    const int tid = threadIdx.x, lane = tid & 31, w = tid >> 5;
    const int g = lane >> 2, tg = lane & 3;
    const int qt = blockIdx.x, h = blockIdx.y, b = blockIdx.z;
    float* ps = smn + OFF_P + w * 16 * APS;

    const size_t base = (size_t)b * SEQ * QKV3 + h * HDIM;
    const float scale = 0.125f;   // folded into Q

    // Load Q tile (scaled, split into tf32 big + small)
#pragma unroll
    for (int l = 0; l < 8; l++) {
        int id = tid + l * 128;
        int r = id >> 4, c = (id & 15) * 4;
        float4 v = *reinterpret_cast<const float4*>(
            &g_qkv[base + (size_t)(qt * 64 + r) * QKV3 + c]);
        v.x *= scale; v.y *= scale; v.z *= scale; v.w *= scale;
        float4 big = f2tf4(v);
        float4 sml = f2tf4(make_float4(v.x - big.x, v.y - big.y,
                                       v.z - big.z, v.w - big.w));
        *reinterpret_cast<float4*>(&qb[r * AQS + c]) = big;
        *reinterpret_cast<float4*>(&qs[r * AQS + c]) = sml;
    }

    float m0 = -CUDART_INF_F, m1 = -CUDART_INF_F;
    float l0 = 0.f, l1 = 0.f;
    float o[8][4];
#pragma unroll
    for (int nf = 0; nf < 8; nf++)
#pragma unroll
        for (int i = 0; i < 4; i++) o[nf][i] = 0.f;

    const int row_g = qt * 64 + w * 16 + g;   // global q row (and +8)
    const int nkt = qt + 1;

    for (int kt = 0; kt < nkt; kt++) {
        __syncthreads();
        // Load K (split) and V (tf32) tiles
#pragma unroll
        for (int l = 0; l < 8; l++) {
            int id = tid + l * 128;
            int r = id >> 4, c = (id & 15) * 4;
            size_t ga = base + (size_t)(kt * 64 + r) * QKV3 + EMBD + c;
            float4 kv = *reinterpret_cast<const float4*>(&g_qkv[ga]);
            float4 big = f2tf4(kv);
            float4 sml = f2tf4(make_float4(kv.x - big.x, kv.y - big.y,
                                           kv.z - big.z, kv.w - big.w));
            *reinterpret_cast<float4*>(&kb[r * AQS + c]) = big;
            *reinterpret_cast<float4*>(&ks[r * AQS + c]) = sml;
            float4 vv = *reinterpret_cast<const float4*>(&g_qkv[ga + EMBD]);
            *reinterpret_cast<float4*>(&vs[r * AVS + c]) = f2tf4(vv);
        }
        __syncthreads();

        // S = Q K^T (tf32x3)
        float s[8][4];
#pragma unroll
        for (int nf = 0; nf < 8; nf++)
#pragma unroll
            for (int i = 0; i < 4; i++) s[nf][i] = 0.f;

#pragma unroll
        for (int kc = 0; kc < 8; kc++) {
            const int d0 = kc * 8;
            const int r0 = w * 16 + g;
            uint32_t ab[4], as2[4];
            ab[0] = __float_as_uint(qb[r0 * AQS + d0 + tg]);
            ab[1] = __float_as_uint(qb[(r0 + 8) * AQS + d0 + tg]);
            ab[2] = __float_as_uint(qb[r0 * AQS + d0 + tg + 4]);
            ab[3] = __float_as_uint(qb[(r0 + 8) * AQS + d0 + tg + 4]);
            as2[0] = __float_as_uint(qs[r0 * AQS + d0 + tg]);
            as2[1] = __float_as_uint(qs[(r0 + 8) * AQS + d0 + tg]);
            as2[2] = __float_as_uint(qs[r0 * AQS + d0 + tg + 4]);
            as2[3] = __float_as_uint(qs[(r0 + 8) * AQS + d0 + tg + 4]);
#pragma unroll
            for (int nf = 0; nf < 8; nf++) {
                const int t0 = nf * 8;
                uint32_t bb[2], bs2[2];
                bb[0] = __float_as_uint(kb[(t0 + g) * AQS + d0 + tg]);
                bb[1] = __float_as_uint(kb[(t0 + g) * AQS + d0 + tg + 4]);
                bs2[0] = __float_as_uint(ks[(t0 + g) * AQS + d0 + tg]);
                bs2[1] = __float_as_uint(ks[(t0 + g) * AQS + d0 + tg + 4]);
                mma_tf32(s[nf], ab, bb);
                mma_tf32(s[nf], as2, bb);
                mma_tf32(s[nf], ab, bs2);
            }
        }

        // Causal mask (diagonal tile only)
        if (kt == qt) {
#pragma unroll
            for (int nf = 0; nf < 8; nf++) {
                int cbase = kt * 64 + nf * 8 + 2 * tg;
                if (cbase > row_g)         s[nf][0] = -CUDART_INF_F;
                if (cbase + 1 > row_g)     s[nf][1] = -CUDART_INF_F;
                if (cbase > row_g + 8)     s[nf][2] = -CUDART_INF_F;
                if (cbase + 1 > row_g + 8) s[nf][3] = -CUDART_INF_F;
            }
        }

        // Online softmax
        float t0m = -CUDART_INF_F, t1m = -CUDART_INF_F;
#pragma unroll
        for (int nf = 0; nf < 8; nf++) {
            t0m = fmaxf(t0m, fmaxf(s[nf][0], s[nf][1]));
            t1m = fmaxf(t1m, fmaxf(s[nf][2], s[nf][3]));
        }
        t0m = fmaxf(t0m, __shfl_xor_sync(0xffffffffu, t0m, 1));
        t0m = fmaxf(t0m, __shfl_xor_sync(0xffffffffu, t0m, 2));
        t1m = fmaxf(t1m, __shfl_xor_sync(0xffffffffu, t1m, 1));
        t1m = fmaxf(t1m, __shfl_xor_sync(0xffffffffu, t1m, 2));

        float mn0 = fmaxf(m0, t0m), mn1 = fmaxf(m1, t1m);
        float c0 = __expf(m0 - mn0), c1 = __expf(m1 - mn1);

        float psum0 = 0.f, psum1 = 0.f;
#pragma unroll
        for (int nf = 0; nf < 8; nf++) {
            float p00 = f2tf(__expf(s[nf][0] - mn0));
            float p01 = f2tf(__expf(s[nf][1] - mn0));
            float p10 = f2tf(__expf(s[nf][2] - mn1));
            float p11 = f2tf(__expf(s[nf][3] - mn1));
            psum0 += p00 + p01;
            psum1 += p10 + p11;
            int cc = nf * 8 + 2 * tg;
            ps[g * APS + cc] = p00;       ps[g * APS + cc + 1] = p01;
            ps[(g + 8) * APS + cc] = p10; ps[(g + 8) * APS + cc + 1] = p11;
        }
        psum0 += __shfl_xor_sync(0xffffffffu, psum0, 1);
        psum0 += __shfl_xor_sync(0xffffffffu, psum0, 2);
        psum1 += __shfl_xor_sync(0xffffffffu, psum1, 1);
        psum1 += __shfl_xor_sync(0xffffffffu, psum1, 2);

        l0 = l0 * c0 + psum0;
        l1 = l1 * c1 + psum1;
        m0 = mn0; m1 = mn1;

#pragma unroll
        for (int nf = 0; nf < 8; nf++) {
            o[nf][0] *= c0; o[nf][1] *= c0;
            o[nf][2] *= c1; o[nf][3] *= c1;
        }

        __syncwarp();   // ps writes visible to warp before A-frag loads

        // O += P @ V (tf32)
#pragma unroll
        for (int kc = 0; kc < 8; kc++) {
            const int t0 = kc * 8;
            uint32_t a[4];
            a[0] = __float_as_uint(ps[g * APS + t0 + tg]);
            a[1] = __float_as_uint(ps[(g + 8) * APS + t0 + tg]);
            a[2] = __float_as_uint(ps[g * APS + t0 + tg + 4]);
            a[3] = __float_as_uint(ps[(g + 8) * APS + t0 + tg + 4]);
#pragma unroll
            for (int nf = 0; nf < 8; nf++) {
                const int d0 = nf * 8;
                uint32_t bv[2];
                bv[0] = __float_as_uint(vs[(t0 + tg) * AVS + d0 + g]);
                bv[1] = __float_as_uint(vs[(t0 + tg + 4) * AVS + d0 + g]);
                mma_tf32(o[nf], a, bv);
            }
        }
    }

    // Epilogue: normalize and store to g_att [B*T, C]
    float inv0 = 1.f / l0, inv1 = 1.f / l1;
    size_t ob = (size_t)b * SEQ * EMBD + h * HDIM;
#pragma unroll
    for (int nf = 0; nf < 8; nf++) {
        int d0 = nf * 8 + 2 * tg;
        float2 v0 = make_float2(o[nf][0] * inv0, o[nf][1] * inv0);
        float2 v1 = make_float2(o[nf][2] * inv1, o[nf][3] * inv1);
        *reinterpret_cast<float2*>(&g_att[ob + (size_t)row_g * EMBD + d0]) = v0;
        *reinterpret_cast<float2*>(&g_att[ob + (size_t)(row_g + 8) * EMBD + d0]) = v1;
    }
}

// ---------------------------------------------------------------------------
// Launch
// ---------------------------------------------------------------------------
extern "C" void kernel_launch(void* const* d_in, const int* in_sizes, int n_in,
                              void* d_out, int out_size)
{
    const float* x      = (const float*)d_in[0];
    const float* w_attn = (const float*)d_in[1];
    const float* b_attn = (const float*)d_in[2];
    const float* w_proj = (const float*)d_in[3];
    const float* b_proj = (const float*)d_in[4];
    float* out = (float*)d_out;

    cudaFuncSetAttribute(flash_attn_kernel,
                         cudaFuncAttributeMaxDynamicSharedMemorySize,
                         ATT_SMEM_BYTES);

    dim3 g1(QKV3 / BN, MTOK / BM);
    qkv_gemm_kernel<<<g1, 256>>>(x, w_attn, b_attn);

    dim3 g2(SEQ / 64, NHEAD, BATCH);
    flash_attn_kernel<<<g2, 128, ATT_SMEM_BYTES>>>();

    dim3 g3(EMBD / BN, MTOK / BM);
    proj_gemm_kernel<<<g3, 256>>>(w_proj, b_proj, out);
}

// round 4
// speedup vs baseline: 4.6038x; 1.2824x over previous
#include <cuda_runtime.h>
#include <cuda_bf16.h>
#include <math_constants.h>
#include <cstdint>

// Problem constants
#define BATCH 4
#define SEQ   2048
#define EMBD  1024
#define NHEAD 16
#define HDIM  64
#define QKV3  (3 * EMBD)
#define MTOK  (BATCH * SEQ)   // 8192 rows

// Scratch (__device__ globals: allowed)
__device__ float g_qkv[(size_t)MTOK * QKV3];   // [B*T, 3C]
__device__ float g_att[(size_t)MTOK * EMBD];   // [B*T, C]

// ---------------------------------------------------------------------------
// Helpers
// ---------------------------------------------------------------------------
__device__ __forceinline__ float f2tf(float x) {
    uint32_t u;
    asm("cvt.rna.tf32.f32 %0, %1;" : "=r"(u) : "f"(x));
    return __uint_as_float(u);
}
__device__ __forceinline__ uint32_t f2tfu(float x) {
    uint32_t u;
    asm("cvt.rna.tf32.f32 %0, %1;" : "=r"(u) : "f"(x));
    return u;
}

__device__ __forceinline__ void mma_tf32(float c[4], const uint32_t a[4],
                                         const uint32_t b[2]) {
    asm volatile(
        "mma.sync.aligned.m16n8k8.row.col.f32.tf32.tf32.f32 "
        "{%0,%1,%2,%3}, {%4,%5,%6,%7}, {%8,%9}, {%0,%1,%2,%3};"
        : "+f"(c[0]), "+f"(c[1]), "+f"(c[2]), "+f"(c[3])
        : "r"(a[0]), "r"(a[1]), "r"(a[2]), "r"(a[3]), "r"(b[0]), "r"(b[1]));
}

__device__ __forceinline__ void mma_bf16(float c[4], const uint32_t a[4],
                                         const uint32_t b[2]) {
    asm volatile(
        "mma.sync.aligned.m16n8k16.row.col.f32.bf16.bf16.f32 "
        "{%0,%1,%2,%3}, {%4,%5,%6,%7}, {%8,%9}, {%0,%1,%2,%3};"
        : "+f"(c[0]), "+f"(c[1]), "+f"(c[2]), "+f"(c[3])
        : "r"(a[0]), "r"(a[1]), "r"(a[2]), "r"(a[3]), "r"(b[0]), "r"(b[1]));
}

__device__ __forceinline__ void cp_async16(void* dst_smem, const void* src) {
    uint32_t sa = (uint32_t)__cvta_generic_to_shared(dst_smem);
    asm volatile("cp.async.cg.shared.global [%0], [%1], 16;\n"
                 :: "r"(sa), "l"(src));
}
__device__ __forceinline__ void cp_commit() {
    asm volatile("cp.async.commit_group;\n");
}
template<int N>
__device__ __forceinline__ void cp_wait() {
    asm volatile("cp.async.wait_group %0;\n" :: "n"(N));
}

__device__ __forceinline__ uint32_t pack_bf(float lo, float hi) {
    __nv_bfloat162 h = __floats2bfloat162_rn(lo, hi);
    return *reinterpret_cast<uint32_t*>(&h);
}

// ---------------------------------------------------------------------------
// TF32 MMA GEMM with 3-stage cp.async pipeline.
// C[M,N] = A[M,K] @ B[K,N] + bias. 128x128x16 tile, 256 threads (8 warps).
// ---------------------------------------------------------------------------
#define BM 128
#define BN 128
#define BK 16
#define ASTR (BK + 4)    // 20 words: A row stride (frag loads conflict-free)
#define BSTR (BN + 8)    // 136 words
#define A_STAGE (BM * ASTR)          // 2560 floats
#define B_STAGE (BK * BSTR)          // 2176 floats
#define GEMM_SMEM_BYTES ((3 * A_STAGE + 3 * B_STAGE) * 4)   // 56832

__device__ __forceinline__ void gemm_body(
    const float* __restrict__ A, const float* __restrict__ Bm,
    const float* __restrict__ bias, float* __restrict__ C,
    int M, int N, int K)
{
    extern __shared__ float gsm[];
    float* As = gsm;                    // [3][BM][ASTR]
    float* Bs = gsm + 3 * A_STAGE;      // [3][BK][BSTR]

    const int tid = threadIdx.x, wid = tid >> 5, lane = tid & 31;
    const int g = lane >> 2, tg = lane & 3;
    const int wm = wid & 3, wn = wid >> 2;
    const int row0 = blockIdx.y * BM, col0 = blockIdx.x * BN;

    float c[2][8][4];
#pragma unroll
    for (int mf = 0; mf < 2; mf++)
#pragma unroll
        for (int nf = 0; nf < 8; nf++)
#pragma unroll
            for (int i = 0; i < 4; i++) c[mf][nf][i] = 0.f;

    // Tile issue: A 512 16B-chunks, B 512 chunks; 2 each per thread.
    auto issue_tile = [&](int kt, int st) {
        float* as0 = As + st * A_STAGE;
        float* bs0 = Bs + st * B_STAGE;
#pragma unroll
        for (int l = 0; l < 2; l++) {
            int id = tid + l * 256;
            int r = id >> 2, cc = (id & 3) * 4;
            cp_async16(&as0[r * ASTR + cc],
                       &A[(size_t)(row0 + r) * K + kt + cc]);
        }
#pragma unroll
        for (int l = 0; l < 2; l++) {
            int id = tid + l * 256;
            int r = id >> 5, cc = (id & 31) * 4;
            cp_async16(&bs0[r * BSTR + cc],
                       &Bm[(size_t)(kt + r) * N + col0 + cc]);
        }
        cp_commit();
    };

    const int nk = K / BK;
    issue_tile(0, 0);
    issue_tile(BK, 1);

    for (int it = 0; it < nk; it++) {
        if (it + 1 < nk) cp_wait<1>(); else cp_wait<0>();
        __syncthreads();

        const int st = it % 3;
        const float* as0 = As + st * A_STAGE;
        const float* bs0 = Bs + st * B_STAGE;

#pragma unroll
        for (int ks = 0; ks < BK; ks += 8) {
            uint32_t a[2][4], b[8][2];
#pragma unroll
            for (int mf = 0; mf < 2; mf++) {
                int m0 = wm * 32 + mf * 16;
                a[mf][0] = f2tfu(as0[(m0 + g) * ASTR + ks + tg]);
                a[mf][1] = f2tfu(as0[(m0 + g + 8) * ASTR + ks + tg]);
                a[mf][2] = f2tfu(as0[(m0 + g) * ASTR + ks + tg + 4]);
                a[mf][3] = f2tfu(as0[(m0 + g + 8) * ASTR + ks + tg + 4]);
            }
#pragma unroll
            for (int nf = 0; nf < 8; nf++) {
                int n0 = wn * 64 + nf * 8;
                b[nf][0] = f2tfu(bs0[(ks + tg) * BSTR + n0 + g]);
                b[nf][1] = f2tfu(bs0[(ks + tg + 4) * BSTR + n0 + g]);
            }
#pragma unroll
            for (int mf = 0; mf < 2; mf++)
#pragma unroll
                for (int nf = 0; nf < 8; nf++)
                    mma_tf32(c[mf][nf], a[mf], b[nf]);
        }

        if (it + 2 < nk) issue_tile((it + 2) * BK, (it + 2) % 3);
    }

#pragma unroll
    for (int mf = 0; mf < 2; mf++) {
        int r_lo = row0 + wm * 32 + mf * 16 + g;
#pragma unroll
        for (int nf = 0; nf < 8; nf++) {
            int cc = col0 + wn * 64 + nf * 8 + tg * 2;
            float b0 = bias[cc], b1 = bias[cc + 1];
            float2 v0 = make_float2(c[mf][nf][0] + b0, c[mf][nf][1] + b1);
            float2 v1 = make_float2(c[mf][nf][2] + b0, c[mf][nf][3] + b1);
            *reinterpret_cast<float2*>(&C[(size_t)r_lo * N + cc]) = v0;
            *reinterpret_cast<float2*>(&C[(size_t)(r_lo + 8) * N + cc]) = v1;
        }
    }
}

__global__ __launch_bounds__(256, 2) void qkv_gemm_kernel(
    const float* __restrict__ x, const float* __restrict__ w,
    const float* __restrict__ bias)
{
    gemm_body(x, w, bias, g_qkv, MTOK, QKV3, EMBD);
}

__global__ __launch_bounds__(256, 2) void proj_gemm_kernel(
    const float* __restrict__ w, const float* __restrict__ bias,
    float* __restrict__ out)
{
    gemm_body(g_att, w, bias, out, MTOK, EMBD, EMBD);
}

// ---------------------------------------------------------------------------
// Tensor-core flash attention (causal).
// Block = (64 q-rows, head, batch), 128 threads = 4 warps, warp owns 16 rows.
// QK^T via bf16x3 (m16n8k16, ~1e-4 score accuracy), PV via single tf32.
// ---------------------------------------------------------------------------
#define QKW 36   // Q/K word stride (= 72 bf16): frag loads conflict-free
#define AVS 72   // V float stride
#define APS 68   // P float stride

#define QB_WORDS (64 * QKW)           // 2304 words per bf16 tile
#define ATT_SMEM_BYTES (4 * QB_WORDS * 4 + 64 * AVS * 4 + 4 * 16 * APS * 4)

__device__ __forceinline__ float4 f2tf4(float4 v) {
    return make_float4(f2tf(v.x), f2tf(v.y), f2tf(v.z), f2tf(v.w));
}

__global__ __launch_bounds__(128) void flash_attn_kernel()
{
    extern __shared__ uint32_t smw[];
    uint32_t* qb = smw;
    uint32_t* qs = qb + QB_WORDS;
    uint32_t* kb = qs + QB_WORDS;
    uint32_t* ks2 = kb + QB_WORDS;
    float* vs = reinterpret_cast<float*>(ks2 + QB_WORDS);

    const int tid = threadIdx.x, lane = tid & 31, w = tid >> 5;
    const int g = lane >> 2, tg = lane & 3;
    const int qt = blockIdx.x, h = blockIdx.y, b = blockIdx.z;
    float* ps = vs + 64 * AVS + w * 16 * APS;

    const size_t base = (size_t)b * SEQ * QKV3 + h * HDIM;
    const float scale = 0.125f;   // 1/sqrt(64), folded into Q

    // Load Q tile (scaled, split into bf16 big + small)
#pragma unroll
    for (int l = 0; l < 8; l++) {
        int id = tid + l * 128;
        int r = id >> 4, c = (id & 15) * 4;
        float4 v = *reinterpret_cast<const float4*>(
            &g_qkv[base + (size_t)(qt * 64 + r) * QKV3 + c]);
        v.x *= scale; v.y *= scale; v.z *= scale; v.w *= scale;
        float bx = __bfloat162float(__float2bfloat16_rn(v.x));
        float by = __bfloat162float(__float2bfloat16_rn(v.y));
        float bz = __bfloat162float(__float2bfloat16_rn(v.z));
        float bw = __bfloat162float(__float2bfloat16_rn(v.w));
        uint2 big = make_uint2(pack_bf(bx, by), pack_bf(bz, bw));
        uint2 sml = make_uint2(pack_bf(v.x - bx, v.y - by),
                               pack_bf(v.z - bz, v.w - bw));
        *reinterpret_cast<uint2*>(&qb[r * QKW + (c >> 1)]) = big;
        *reinterpret_cast<uint2*>(&qs[r * QKW + (c >> 1)]) = sml;
    }

    float m0 = -CUDART_INF_F, m1 = -CUDART_INF_F;
    float l0 = 0.f, l1 = 0.f;
    float o[8][4];
#pragma unroll
    for (int nf = 0; nf < 8; nf++)
#pragma unroll
        for (int i = 0; i < 4; i++) o[nf][i] = 0.f;

    const int row_g = qt * 64 + w * 16 + g;   // global q row (and +8)
    const int nkt = qt + 1;

    for (int kt = 0; kt < nkt; kt++) {
        __syncthreads();
        // Load K (bf16 split) and V (tf32) tiles
#pragma unroll
        for (int l = 0; l < 8; l++) {
            int id = tid + l * 128;
            int r = id >> 4, c = (id & 15) * 4;
            size_t ga = base + (size_t)(kt * 64 + r) * QKV3 + EMBD + c;
            float4 kv = *reinterpret_cast<const float4*>(&g_qkv[ga]);
            float bx = __bfloat162float(__float2bfloat16_rn(kv.x));
            float by = __bfloat162float(__float2bfloat16_rn(kv.y));
            float bz = __bfloat162float(__float2bfloat16_rn(kv.z));
            float bw = __bfloat162float(__float2bfloat16_rn(kv.w));
            uint2 big = make_uint2(pack_bf(bx, by), pack_bf(bz, bw));
            uint2 sml = make_uint2(pack_bf(kv.x - bx, kv.y - by),
                                   pack_bf(kv.z - bz, kv.w - bw));
            *reinterpret_cast<uint2*>(&kb[r * QKW + (c >> 1)]) = big;
            *reinterpret_cast<uint2*>(&ks2[r * QKW + (c >> 1)]) = sml;
            float4 vv = *reinterpret_cast<const float4*>(&g_qkv[ga + EMBD]);
            *reinterpret_cast<float4*>(&vs[r * AVS + c]) = f2tf4(vv);
        }
        __syncthreads();

        // S = Q K^T (bf16x3, m16n8k16): 4 K-chunks of 16
        float s[8][4];
#pragma unroll
        for (int nf = 0; nf < 8; nf++)
#pragma unroll
            for (int i = 0; i < 4; i++) s[nf][i] = 0.f;

#pragma unroll
        for (int kc = 0; kc < 4; kc++) {
            const int d0w = kc * 8;             // word offset (16 halfs)
            const int r0 = w * 16 + g;
            uint32_t ab[4], as2[4];
            ab[0] = qb[r0 * QKW + d0w + tg];
            ab[1] = qb[(r0 + 8) * QKW + d0w + tg];
            ab[2] = qb[r0 * QKW + d0w + tg + 4];
            ab[3] = qb[(r0 + 8) * QKW + d0w + tg + 4];
            as2[0] = qs[r0 * QKW + d0w + tg];
            as2[1] = qs[(r0 + 8) * QKW + d0w + tg];
            as2[2] = qs[r0 * QKW + d0w + tg + 4];
            as2[3] = qs[(r0 + 8) * QKW + d0w + tg + 4];
#pragma unroll
            for (int nf = 0; nf < 8; nf++) {
                const int t0 = nf * 8;
                uint32_t bb[2], bs[2];
                bb[0] = kb[(t0 + g) * QKW + d0w + tg];
                bb[1] = kb[(t0 + g) * QKW + d0w + tg + 4];
                bs[0] = ks2[(t0 + g) * QKW + d0w + tg];
                bs[1] = ks2[(t0 + g) * QKW + d0w + tg + 4];
                mma_bf16(s[nf], ab, bb);
                mma_bf16(s[nf], as2, bb);
                mma_bf16(s[nf], ab, bs);
            }
        }

        // Causal mask (diagonal tile only)
        if (kt == qt) {
#pragma unroll
            for (int nf = 0; nf < 8; nf++) {
                int cbase = kt * 64 + nf * 8 + 2 * tg;
                if (cbase > row_g)         s[nf][0] = -CUDART_INF_F;
                if (cbase + 1 > row_g)     s[nf][1] = -CUDART_INF_F;
                if (cbase > row_g + 8)     s[nf][2] = -CUDART_INF_F;
                if (cbase + 1 > row_g + 8) s[nf][3] = -CUDART_INF_F;
            }
        }

        // Online softmax
        float t0m = -CUDART_INF_F, t1m = -CUDART_INF_F;
#pragma unroll
        for (int nf = 0; nf < 8; nf++) {
            t0m = fmaxf(t0m, fmaxf(s[nf][0], s[nf][1]));
            t1m = fmaxf(t1m, fmaxf(s[nf][2], s[nf][3]));
        }
        t0m = fmaxf(t0m, __shfl_xor_sync(0xffffffffu, t0m, 1));
        t0m = fmaxf(t0m, __shfl_xor_sync(0xffffffffu, t0m, 2));
        t1m = fmaxf(t1m, __shfl_xor_sync(0xffffffffu, t1m, 1));
        t1m = fmaxf(t1m, __shfl_xor_sync(0xffffffffu, t1m, 2));

        float mn0 = fmaxf(m0, t0m), mn1 = fmaxf(m1, t1m);
        float c0 = __expf(m0 - mn0), c1 = __expf(m1 - mn1);

        float psum0 = 0.f, psum1 = 0.f;
#pragma unroll
        for (int nf = 0; nf < 8; nf++) {
            float p00 = f2tf(__expf(s[nf][0] - mn0));
            float p01 = f2tf(__expf(s[nf][1] - mn0));
            float p10 = f2tf(__expf(s[nf][2] - mn1));
            float p11 = f2tf(__expf(s[nf][3] - mn1));
            psum0 += p00 + p01;
            psum1 += p10 + p11;
            int cc = nf * 8 + 2 * tg;
            ps[g * APS + cc] = p00;       ps[g * APS + cc + 1] = p01;
            ps[(g + 8) * APS + cc] = p10; ps[(g + 8) * APS + cc + 1] = p11;
        }
        psum0 += __shfl_xor_sync(0xffffffffu, psum0, 1);
        psum0 += __shfl_xor_sync(0xffffffffu, psum0, 2);
        psum1 += __shfl_xor_sync(0xffffffffu, psum1, 1);
        psum1 += __shfl_xor_sync(0xffffffffu, psum1, 2);

        l0 = l0 * c0 + psum0;
        l1 = l1 * c1 + psum1;
        m0 = mn0; m1 = mn1;

#pragma unroll
        for (int nf = 0; nf < 8; nf++) {
            o[nf][0] *= c0; o[nf][1] *= c0;
            o[nf][2] *= c1; o[nf][3] *= c1;
        }

        __syncwarp();   // ps writes visible to warp before A-frag loads

        // O += P @ V (tf32, m16n8k8)
#pragma unroll
        for (int kc = 0; kc < 8; kc++) {
            const int t0 = kc * 8;
            uint32_t a[4];
            a[0] = __float_as_uint(ps[g * APS + t0 + tg]);
            a[1] = __float_as_uint(ps[(g + 8) * APS + t0 + tg]);
            a[2] = __float_as_uint(ps[g * APS + t0 + tg + 4]);
            a[3] = __float_as_uint(ps[(g + 8) * APS + t0 + tg + 4]);
#pragma unroll
            for (int nf = 0; nf < 8; nf++) {
                const int d0 = nf * 8;
                uint32_t bv[2];
                bv[0] = __float_as_uint(vs[(t0 + tg) * AVS + d0 + g]);
                bv[1] = __float_as_uint(vs[(t0 + tg + 4) * AVS + d0 + g]);
                mma_tf32(o[nf], a, bv);
            }
        }
    }

    // Epilogue: normalize and store to g_att [B*T, C]
    float inv0 = 1.f / l0, inv1 = 1.f / l1;
    size_t ob = (size_t)b * SEQ * EMBD + h * HDIM;
#pragma unroll
    for (int nf = 0; nf < 8; nf++) {
        int d0 = nf * 8 + 2 * tg;
        float2 v0 = make_float2(o[nf][0] * inv0, o[nf][1] * inv0);
        float2 v1 = make_float2(o[nf][2] * inv1, o[nf][3] * inv1);
        *reinterpret_cast<float2*>(&g_att[ob + (size_t)row_g * EMBD + d0]) = v0;
        *reinterpret_cast<float2*>(&g_att[ob + (size_t)(row_g + 8) * EMBD + d0]) = v1;
    }
}

// ---------------------------------------------------------------------------
// Launch
// ---------------------------------------------------------------------------
extern "C" void kernel_launch(void* const* d_in, const int* in_sizes, int n_in,
                              void* d_out, int out_size)
{
    const float* x      = (const float*)d_in[0];
    const float* w_attn = (const float*)d_in[1];
    const float* b_attn = (const float*)d_in[2];
    const float* w_proj = (const float*)d_in[3];
    const float* b_proj = (const float*)d_in[4];
    float* out = (float*)d_out;

    cudaFuncSetAttribute(qkv_gemm_kernel,
                         cudaFuncAttributeMaxDynamicSharedMemorySize,
                         GEMM_SMEM_BYTES);
    cudaFuncSetAttribute(proj_gemm_kernel,
                         cudaFuncAttributeMaxDynamicSharedMemorySize,
                         GEMM_SMEM_BYTES);
    cudaFuncSetAttribute(flash_attn_kernel,
                         cudaFuncAttributeMaxDynamicSharedMemorySize,
                         ATT_SMEM_BYTES);

    dim3 g1(QKV3 / BN, MTOK / BM);
    qkv_gemm_kernel<<<g1, 256, GEMM_SMEM_BYTES>>>(x, w_attn, b_attn);

    dim3 g2(SEQ / 64, NHEAD, BATCH);
    flash_attn_kernel<<<g2, 128, ATT_SMEM_BYTES>>>();

    dim3 g3(EMBD / BN, MTOK / BM);
    proj_gemm_kernel<<<g3, 256, GEMM_SMEM_BYTES>>>(w_proj, b_proj, out);
}

// round 5
// speedup vs baseline: 5.0509x; 1.0971x over previous
#include <cuda_runtime.h>
#include <cuda_bf16.h>
#include <math_constants.h>
#include <cstdint>

// Problem constants
#define BATCH 4
#define SEQ   2048
#define EMBD  1024
#define NHEAD 16
#define HDIM  64
#define QKV3  (3 * EMBD)
#define MTOK  (BATCH * SEQ)   // 8192 rows

// Scratch (__device__ globals: allowed)
__device__ float    g_xt [(size_t)MTOK * EMBD];       // x, tf32-rounded
__device__ float    g_wat[(size_t)EMBD * QKV3];       // w_attn, tf32-rounded
__device__ float    g_wpt[(size_t)EMBD * EMBD];       // w_proj, tf32-rounded
__device__ float    g_q  [(size_t)MTOK * EMBD];       // Q fp32
__device__ uint32_t g_kb [(size_t)MTOK * EMBD / 2];   // K bf16 "big" pairs
__device__ uint32_t g_ks [(size_t)MTOK * EMBD / 2];   // K bf16 "small" pairs
__device__ float    g_vt [(size_t)MTOK * EMBD];       // V tf32-rounded
__device__ float    g_att[(size_t)MTOK * EMBD];       // attn out, tf32-rounded

// ---------------------------------------------------------------------------
// Helpers
// ---------------------------------------------------------------------------
__device__ __forceinline__ float f2tf(float x) {
    uint32_t u;
    asm("cvt.rna.tf32.f32 %0, %1;" : "=r"(u) : "f"(x));
    return __uint_as_float(u);
}
__device__ __forceinline__ float4 f2tf4(float4 v) {
    return make_float4(f2tf(v.x), f2tf(v.y), f2tf(v.z), f2tf(v.w));
}
__device__ __forceinline__ float bfr(float x) {
    return __bfloat162float(__float2bfloat16_rn(x));
}
__device__ __forceinline__ uint32_t pack_bf(float lo, float hi) {
    __nv_bfloat162 h = __floats2bfloat162_rn(lo, hi);
    return *reinterpret_cast<uint32_t*>(&h);
}

__device__ __forceinline__ void mma_tf32(float c[4], const uint32_t a[4],
                                         const uint32_t b[2]) {
    asm volatile(
        "mma.sync.aligned.m16n8k8.row.col.f32.tf32.tf32.f32 "
        "{%0,%1,%2,%3}, {%4,%5,%6,%7}, {%8,%9}, {%0,%1,%2,%3};"
        : "+f"(c[0]), "+f"(c[1]), "+f"(c[2]), "+f"(c[3])
        : "r"(a[0]), "r"(a[1]), "r"(a[2]), "r"(a[3]), "r"(b[0]), "r"(b[1]));
}
__device__ __forceinline__ void mma_bf16(float c[4], const uint32_t a[4],
                                         const uint32_t b[2]) {
    asm volatile(
        "mma.sync.aligned.m16n8k16.row.col.f32.bf16.bf16.f32 "
        "{%0,%1,%2,%3}, {%4,%5,%6,%7}, {%8,%9}, {%0,%1,%2,%3};"
        : "+f"(c[0]), "+f"(c[1]), "+f"(c[2]), "+f"(c[3])
        : "r"(a[0]), "r"(a[1]), "r"(a[2]), "r"(a[3]), "r"(b[0]), "r"(b[1]));
}

__device__ __forceinline__ void cp_async16(void* dst_smem, const void* src) {
    uint32_t sa = (uint32_t)__cvta_generic_to_shared(dst_smem);
    asm volatile("cp.async.cg.shared.global [%0], [%1], 16;\n"
                 :: "r"(sa), "l"(src));
}
__device__ __forceinline__ void cp_commit() {
    asm volatile("cp.async.commit_group;\n");
}
template<int N>
__device__ __forceinline__ void cp_wait() {
    asm volatile("cp.async.wait_group %0;\n" :: "n"(N));
}

// ---------------------------------------------------------------------------
// Prep: tf32-round x, w_attn, w_proj (one pass, float4 granularity)
// ---------------------------------------------------------------------------
#define X4  ((size_t)MTOK * EMBD / 4)     // 2097152
#define WA4 ((size_t)EMBD * QKV3 / 4)     // 786432
#define WP4 ((size_t)EMBD * EMBD / 4)     // 262144
#define PREP_TOTAL (X4 + WA4 + WP4)       // 3145728

__global__ __launch_bounds__(256) void prep_round_kernel(
    const float* __restrict__ x, const float* __restrict__ wa,
    const float* __restrict__ wp)
{
    size_t i = (size_t)blockIdx.x * 256 + threadIdx.x;
    if (i < X4) {
        float4 v = reinterpret_cast<const float4*>(x)[i];
        reinterpret_cast<float4*>(g_xt)[i] = f2tf4(v);
    } else if (i < X4 + WA4) {
        size_t j = i - X4;
        float4 v = reinterpret_cast<const float4*>(wa)[j];
        reinterpret_cast<float4*>(g_wat)[j] = f2tf4(v);
    } else if (i < PREP_TOTAL) {
        size_t j = i - X4 - WA4;
        float4 v = reinterpret_cast<const float4*>(wp)[j];
        reinterpret_cast<float4*>(g_wpt)[j] = f2tf4(v);
    }
}

// ---------------------------------------------------------------------------
// TF32 MMA GEMM, 3-stage cp.async pipeline. Operands pre-rounded to tf32.
// mode 0: plain store to C.  mode 1: qkv split epilogue (Q fp32 / K bf16
// big+small / V tf32) into the attention-ready buffers.
// ---------------------------------------------------------------------------
#define BM 128
#define BN 128
#define BK 16
#define ASTR (BK + 4)
#define BSTR (BN + 8)
#define A_STAGE (BM * ASTR)
#define B_STAGE (BK * BSTR)
#define GEMM_SMEM_BYTES ((3 * A_STAGE + 3 * B_STAGE) * 4)

__device__ __forceinline__ void gemm_body(
    const float* __restrict__ A, const float* __restrict__ Bm,
    const float* __restrict__ bias, float* __restrict__ C,
    int M, int N, int K, int mode)
{
    extern __shared__ float gsm[];
    float* As = gsm;
    float* Bs = gsm + 3 * A_STAGE;

    const int tid = threadIdx.x, wid = tid >> 5, lane = tid & 31;
    const int g = lane >> 2, tg = lane & 3;
    const int wm = wid & 3, wn = wid >> 2;
    const int row0 = blockIdx.y * BM, col0 = blockIdx.x * BN;

    float c[2][8][4];
#pragma unroll
    for (int mf = 0; mf < 2; mf++)
#pragma unroll
        for (int nf = 0; nf < 8; nf++)
#pragma unroll
            for (int i = 0; i < 4; i++) c[mf][nf][i] = 0.f;

    auto issue_tile = [&](int kt, int st) {
        float* as0 = As + st * A_STAGE;
        float* bs0 = Bs + st * B_STAGE;
#pragma unroll
        for (int l = 0; l < 2; l++) {
            int id = tid + l * 256;
            int r = id >> 2, cc = (id & 3) * 4;
            cp_async16(&as0[r * ASTR + cc],
                       &A[(size_t)(row0 + r) * K + kt + cc]);
        }
#pragma unroll
        for (int l = 0; l < 2; l++) {
            int id = tid + l * 256;
            int r = id >> 5, cc = (id & 31) * 4;
            cp_async16(&bs0[r * BSTR + cc],
                       &Bm[(size_t)(kt + r) * N + col0 + cc]);
        }
        cp_commit();
    };

    const int nk = K / BK;
    issue_tile(0, 0);
    issue_tile(BK, 1);

    for (int it = 0; it < nk; it++) {
        if (it + 1 < nk) cp_wait<1>(); else cp_wait<0>();
        __syncthreads();

        const int st = it % 3;
        const float* as0 = As + st * A_STAGE;
        const float* bs0 = Bs + st * B_STAGE;

#pragma unroll
        for (int ks = 0; ks < BK; ks += 8) {
            uint32_t a[2][4], b[8][2];
#pragma unroll
            for (int mf = 0; mf < 2; mf++) {
                int m0 = wm * 32 + mf * 16;
                a[mf][0] = __float_as_uint(as0[(m0 + g) * ASTR + ks + tg]);
                a[mf][1] = __float_as_uint(as0[(m0 + g + 8) * ASTR + ks + tg]);
                a[mf][2] = __float_as_uint(as0[(m0 + g) * ASTR + ks + tg + 4]);
                a[mf][3] = __float_as_uint(as0[(m0 + g + 8) * ASTR + ks + tg + 4]);
            }
#pragma unroll
            for (int nf = 0; nf < 8; nf++) {
                int n0 = wn * 64 + nf * 8;
                b[nf][0] = __float_as_uint(bs0[(ks + tg) * BSTR + n0 + g]);
                b[nf][1] = __float_as_uint(bs0[(ks + tg + 4) * BSTR + n0 + g]);
            }
#pragma unroll
            for (int mf = 0; mf < 2; mf++)
#pragma unroll
                for (int nf = 0; nf < 8; nf++)
                    mma_tf32(c[mf][nf], a[mf], b[nf]);
        }

        if (it + 2 < nk) issue_tile((it + 2) * BK, (it + 2) % 3);
    }

    // region of this CTA's column block (uniform: col0 multiple of 128)
    const int region = col0 >> 10;   // 0=Q, 1=K, 2=V (mode 1 only)

#pragma unroll
    for (int mf = 0; mf < 2; mf++) {
        int r_lo = row0 + wm * 32 + mf * 16 + g;
#pragma unroll
        for (int nf = 0; nf < 8; nf++) {
            int cc = col0 + wn * 64 + nf * 8 + tg * 2;
            float b0 = bias[cc], b1 = bias[cc + 1];
            float v00 = c[mf][nf][0] + b0, v01 = c[mf][nf][1] + b1;  // row r_lo
            float v10 = c[mf][nf][2] + b0, v11 = c[mf][nf][3] + b1;  // row r_lo+8
            if (mode == 0) {
                *reinterpret_cast<float2*>(&C[(size_t)r_lo * N + cc]) =
                    make_float2(v00, v01);
                *reinterpret_cast<float2*>(&C[(size_t)(r_lo + 8) * N + cc]) =
                    make_float2(v10, v11);
            } else if (region == 0) {
                *reinterpret_cast<float2*>(&g_q[(size_t)r_lo * EMBD + cc]) =
                    make_float2(v00, v01);
                *reinterpret_cast<float2*>(&g_q[(size_t)(r_lo + 8) * EMBD + cc]) =
                    make_float2(v10, v11);
            } else if (region == 1) {
                int col = cc - EMBD;
                float h00 = bfr(v00), h01 = bfr(v01);
                float h10 = bfr(v10), h11 = bfr(v11);
                size_t w0 = ((size_t)r_lo * EMBD + col) >> 1;
                size_t w1 = ((size_t)(r_lo + 8) * EMBD + col) >> 1;
                g_kb[w0] = pack_bf(h00, h01);
                g_ks[w0] = pack_bf(v00 - h00, v01 - h01);
                g_kb[w1] = pack_bf(h10, h11);
                g_ks[w1] = pack_bf(v10 - h10, v11 - h11);
            } else {
                int col = cc - 2 * EMBD;
                *reinterpret_cast<float2*>(&g_vt[(size_t)r_lo * EMBD + col]) =
                    make_float2(f2tf(v00), f2tf(v01));
                *reinterpret_cast<float2*>(&g_vt[(size_t)(r_lo + 8) * EMBD + col]) =
                    make_float2(f2tf(v10), f2tf(v11));
            }
        }
    }
}

__global__ __launch_bounds__(256, 2) void qkv_gemm_kernel(
    const float* __restrict__ bias)
{
    gemm_body(g_xt, g_wat, bias, nullptr, MTOK, QKV3, EMBD, 1);
}

__global__ __launch_bounds__(256, 2) void proj_gemm_kernel(
    const float* __restrict__ bias, float* __restrict__ out)
{
    gemm_body(g_att, g_wpt, bias, out, MTOK, EMBD, EMBD, 0);
}

// ---------------------------------------------------------------------------
// Tensor-core flash attention (causal), pre-converted operands, 2-stage
// cp.async double buffer on K/V tiles.
// Block = (64 q-rows, head, batch), 128 threads = 4 warps, warp owns 16 rows.
// QK^T via bf16x3 (m16n8k16), PV via single tf32.
// ---------------------------------------------------------------------------
#define QKW 36                       // K/Q smem word stride (72 halfs)
#define AVS 72                       // V smem float stride
#define APS 68                       // P smem float stride
#define QBW (64 * QKW)               // 2304 words per bf16 tile
#define STAGE_W (QBW + QBW + 64 * AVS)         // kb + ks + vs = 9216 words
#define OFF_ST0 (2 * QBW)                       // after qb, qs
#define OFF_P   (OFF_ST0 + 2 * STAGE_W)         // 23040
#define ATT_SMEM_BYTES ((OFF_P + 4 * 16 * APS) * 4)   // 109568

__global__ __launch_bounds__(128) void flash_attn_kernel()
{
    extern __shared__ uint32_t smw[];
    uint32_t* qb = smw;
    uint32_t* qs = smw + QBW;

    const int tid = threadIdx.x, lane = tid & 31, w = tid >> 5;
    const int g = lane >> 2, tg = lane & 3;
    const int qt = blockIdx.x, h = blockIdx.y, b = blockIdx.z;
    float* ps = reinterpret_cast<float*>(smw + OFF_P) + w * 16 * APS;

    const int bsq = b * SEQ;
    const float scale = 0.125f;   // 1/sqrt(64), folded into Q

    // K/V tile issue via cp.async (raw copy of pre-converted data)
    auto issue_kv = [&](int kt, int st) {
        uint32_t* kbs = smw + OFF_ST0 + st * STAGE_W;
        uint32_t* kss = kbs + QBW;
        float* vss = reinterpret_cast<float*>(kss + QBW);
#pragma unroll
        for (int l = 0; l < 4; l++) {           // kb: 512 16B chunks
            int id = tid + l * 128;
            int r = id >> 3, ch = id & 7;
            cp_async16(&kbs[r * QKW + ch * 4],
                       &g_kb[(size_t)(bsq + kt * 64 + r) * 512 + h * 32 + ch * 4]);
        }
#pragma unroll
        for (int l = 0; l < 4; l++) {           // ks: 512 chunks
            int id = tid + l * 128;
            int r = id >> 3, ch = id & 7;
            cp_async16(&kss[r * QKW + ch * 4],
                       &g_ks[(size_t)(bsq + kt * 64 + r) * 512 + h * 32 + ch * 4]);
        }
#pragma unroll
        for (int l = 0; l < 8; l++) {           // vs: 1024 chunks
            int id = tid + l * 128;
            int r = id >> 4, ch = id & 15;
            cp_async16(&vss[r * AVS + ch * 4],
                       &g_vt[(size_t)(bsq + kt * 64 + r) * EMBD + h * HDIM + ch * 4]);
        }
        cp_commit();
    };

    issue_kv(0, 0);

    // Load Q tile (scaled, split into bf16 big + small)
#pragma unroll
    for (int l = 0; l < 8; l++) {
        int id = tid + l * 128;
        int r = id >> 4, c = (id & 15) * 4;
        float4 v = *reinterpret_cast<const float4*>(
            &g_q[(size_t)(bsq + qt * 64 + r) * EMBD + h * HDIM + c]);
        v.x *= scale; v.y *= scale; v.z *= scale; v.w *= scale;
        float bx = bfr(v.x), by = bfr(v.y), bz = bfr(v.z), bw = bfr(v.w);
        *reinterpret_cast<uint2*>(&qb[r * QKW + (c >> 1)]) =
            make_uint2(pack_bf(bx, by), pack_bf(bz, bw));
        *reinterpret_cast<uint2*>(&qs[r * QKW + (c >> 1)]) =
            make_uint2(pack_bf(v.x - bx, v.y - by), pack_bf(v.z - bz, v.w - bw));
    }

    float m0 = -CUDART_INF_F, m1 = -CUDART_INF_F;
    float l0 = 0.f, l1 = 0.f;
    float o[8][4];
#pragma unroll
    for (int nf = 0; nf < 8; nf++)
#pragma unroll
        for (int i = 0; i < 4; i++) o[nf][i] = 0.f;

    const int row_g = qt * 64 + w * 16 + g;
    const int nkt = qt + 1;

    for (int kt = 0; kt < nkt; kt++) {
        if (kt + 1 < nkt) { issue_kv(kt + 1, (kt + 1) & 1); cp_wait<1>(); }
        else cp_wait<0>();
        __syncthreads();

        const int st = kt & 1;
        const uint32_t* kbs = smw + OFF_ST0 + st * STAGE_W;
        const uint32_t* kss = kbs + QBW;
        const float* vss = reinterpret_cast<const float*>(kss + QBW);

        // S = Q K^T (bf16x3, m16n8k16)
        float s[8][4];
#pragma unroll
        for (int nf = 0; nf < 8; nf++)
#pragma unroll
            for (int i = 0; i < 4; i++) s[nf][i] = 0.f;

#pragma unroll
        for (int kc = 0; kc < 4; kc++) {
            const int d0w = kc * 8;
            const int r0 = w * 16 + g;
            uint32_t ab[4], as2[4];
            ab[0] = qb[r0 * QKW + d0w + tg];
            ab[1] = qb[(r0 + 8) * QKW + d0w + tg];
            ab[2] = qb[r0 * QKW + d0w + tg + 4];
            ab[3] = qb[(r0 + 8) * QKW + d0w + tg + 4];
            as2[0] = qs[r0 * QKW + d0w + tg];
            as2[1] = qs[(r0 + 8) * QKW + d0w + tg];
            as2[2] = qs[r0 * QKW + d0w + tg + 4];
            as2[3] = qs[(r0 + 8) * QKW + d0w + tg + 4];
#pragma unroll
            for (int nf = 0; nf < 8; nf++) {
                const int t0 = nf * 8;
                uint32_t bb[2], bs[2];
                bb[0] = kbs[(t0 + g) * QKW + d0w + tg];
                bb[1] = kbs[(t0 + g) * QKW + d0w + tg + 4];
                bs[0] = kss[(t0 + g) * QKW + d0w + tg];
                bs[1] = kss[(t0 + g) * QKW + d0w + tg + 4];
                mma_bf16(s[nf], ab, bb);
                mma_bf16(s[nf], as2, bb);
                mma_bf16(s[nf], ab, bs);
            }
        }

        // Causal mask (diagonal tile only)
        if (kt == qt) {
#pragma unroll
            for (int nf = 0; nf < 8; nf++) {
                int cbase = kt * 64 + nf * 8 + 2 * tg;
                if (cbase > row_g)         s[nf][0] = -CUDART_INF_F;
                if (cbase + 1 > row_g)     s[nf][1] = -CUDART_INF_F;
                if (cbase > row_g + 8)     s[nf][2] = -CUDART_INF_F;
                if (cbase + 1 > row_g + 8) s[nf][3] = -CUDART_INF_F;
            }
        }

        // Online softmax
        float t0m = -CUDART_INF_F, t1m = -CUDART_INF_F;
#pragma unroll
        for (int nf = 0; nf < 8; nf++) {
            t0m = fmaxf(t0m, fmaxf(s[nf][0], s[nf][1]));
            t1m = fmaxf(t1m, fmaxf(s[nf][2], s[nf][3]));
        }
        t0m = fmaxf(t0m, __shfl_xor_sync(0xffffffffu, t0m, 1));
        t0m = fmaxf(t0m, __shfl_xor_sync(0xffffffffu, t0m, 2));
        t1m = fmaxf(t1m, __shfl_xor_sync(0xffffffffu, t1m, 1));
        t1m = fmaxf(t1m, __shfl_xor_sync(0xffffffffu, t1m, 2));

        float mn0 = fmaxf(m0, t0m), mn1 = fmaxf(m1, t1m);
        float c0 = __expf(m0 - mn0), c1 = __expf(m1 - mn1);

        float psum0 = 0.f, psum1 = 0.f;
#pragma unroll
        for (int nf = 0; nf < 8; nf++) {
            float p00 = f2tf(__expf(s[nf][0] - mn0));
            float p01 = f2tf(__expf(s[nf][1] - mn0));
            float p10 = f2tf(__expf(s[nf][2] - mn1));
            float p11 = f2tf(__expf(s[nf][3] - mn1));
            psum0 += p00 + p01;
            psum1 += p10 + p11;
            int cc = nf * 8 + 2 * tg;
            ps[g * APS + cc] = p00;       ps[g * APS + cc + 1] = p01;
            ps[(g + 8) * APS + cc] = p10; ps[(g + 8) * APS + cc + 1] = p11;
        }
        psum0 += __shfl_xor_sync(0xffffffffu, psum0, 1);
        psum0 += __shfl_xor_sync(0xffffffffu, psum0, 2);
        psum1 += __shfl_xor_sync(0xffffffffu, psum1, 1);
        psum1 += __shfl_xor_sync(0xffffffffu, psum1, 2);

        l0 = l0 * c0 + psum0;
        l1 = l1 * c1 + psum1;
        m0 = mn0; m1 = mn1;

#pragma unroll
        for (int nf = 0; nf < 8; nf++) {
            o[nf][0] *= c0; o[nf][1] *= c0;
            o[nf][2] *= c1; o[nf][3] *= c1;
        }

        __syncwarp();

        // O += P @ V (tf32, m16n8k8)
#pragma unroll
        for (int kc = 0; kc < 8; kc++) {
            const int t0 = kc * 8;
            uint32_t a[4];
            a[0] = __float_as_uint(ps[g * APS + t0 + tg]);
            a[1] = __float_as_uint(ps[(g + 8) * APS + t0 + tg]);
            a[2] = __float_as_uint(ps[g * APS + t0 + tg + 4]);
            a[3] = __float_as_uint(ps[(g + 8) * APS + t0 + tg + 4]);
#pragma unroll
            for (int nf = 0; nf < 8; nf++) {
                const int d0 = nf * 8;
                uint32_t bv[2];
                bv[0] = __float_as_uint(vss[(t0 + tg) * AVS + d0 + g]);
                bv[1] = __float_as_uint(vss[(t0 + tg + 4) * AVS + d0 + g]);
                mma_tf32(o[nf], a, bv);
            }
        }
        __syncthreads();   // stage reuse protection before next issue
    }

    // Epilogue: normalize, tf32-round (proj A operand), store g_att [B*T, C]
    float inv0 = 1.f / l0, inv1 = 1.f / l1;
    size_t ob = (size_t)bsq * EMBD + h * HDIM;
#pragma unroll
    for (int nf = 0; nf < 8; nf++) {
        int d0 = nf * 8 + 2 * tg;
        float2 v0 = make_float2(f2tf(o[nf][0] * inv0), f2tf(o[nf][1] * inv0));
        float2 v1 = make_float2(f2tf(o[nf][2] * inv1), f2tf(o[nf][3] * inv1));
        *reinterpret_cast<float2*>(&g_att[ob + (size_t)row_g * EMBD + d0]) = v0;
        *reinterpret_cast<float2*>(&g_att[ob + (size_t)(row_g + 8) * EMBD + d0]) = v1;
    }
}

// ---------------------------------------------------------------------------
// Launch
// ---------------------------------------------------------------------------
extern "C" void kernel_launch(void* const* d_in, const int* in_sizes, int n_in,
                              void* d_out, int out_size)
{
    const float* x      = (const float*)d_in[0];
    const float* w_attn = (const float*)d_in[1];
    const float* b_attn = (const float*)d_in[2];
    const float* w_proj = (const float*)d_in[3];
    const float* b_proj = (const float*)d_in[4];
    float* out = (float*)d_out;

    cudaFuncSetAttribute(qkv_gemm_kernel,
                         cudaFuncAttributeMaxDynamicSharedMemorySize,
                         GEMM_SMEM_BYTES);
    cudaFuncSetAttribute(proj_gemm_kernel,
                         cudaFuncAttributeMaxDynamicSharedMemorySize,
                         GEMM_SMEM_BYTES);
    cudaFuncSetAttribute(flash_attn_kernel,
                         cudaFuncAttributeMaxDynamicSharedMemorySize,
                         ATT_SMEM_BYTES);

    prep_round_kernel<<<(unsigned)(PREP_TOTAL / 256), 256>>>(x, w_attn, w_proj);

    dim3 g1(QKV3 / BN, MTOK / BM);
    qkv_gemm_kernel<<<g1, 256, GEMM_SMEM_BYTES>>>(b_attn);

    dim3 g2(SEQ / 64, NHEAD, BATCH);
    flash_attn_kernel<<<g2, 128, ATT_SMEM_BYTES>>>();

    dim3 g3(EMBD / BN, MTOK / BM);
    proj_gemm_kernel<<<g3, 256, GEMM_SMEM_BYTES>>>(b_proj, out);
}

// round 9
// speedup vs baseline: 5.5284x; 1.0945x over previous
#include <cuda_runtime.h>
#include <cuda_bf16.h>
#include <math_constants.h>
#include <cstdint>

// Problem constants
#define BATCH 4
#define SEQ   2048
#define EMBD  1024
#define NHEAD 16
#define HDIM  64
#define QKV3  (3 * EMBD)
#define MTOK  (BATCH * SEQ)   // 8192
#define KD8   (EMBD / 8)      // 128 k-tiles of 8 (K = 1024 for both GEMMs)

// ---------------------------------------------------------------------------
// Scratch (__device__ globals) — fragment-major GEMM operands + attn buffers
// A-frag layout [M/16][K/8][lane 32][slot 4] floats
// B-frag layout [N/8][K/8][lane 32][slot 2] floats
// ---------------------------------------------------------------------------
__device__ __align__(16) float    g_xf [(size_t)MTOK * EMBD];     // x (tf32)
__device__ __align__(16) float    g_wfa[(size_t)EMBD * QKV3];     // w_attn^T (tf32)
__device__ __align__(16) float    g_wfp[(size_t)EMBD * EMBD];     // w_proj^T (tf32)
__device__ __align__(16) float    g_af [(size_t)MTOK * EMBD];     // attn out (tf32)
__device__ __align__(16) float    g_q  [(size_t)MTOK * EMBD];     // Q fp32
__device__ __align__(16) uint32_t g_kb [(size_t)MTOK * EMBD / 2]; // K bf16 big
__device__ __align__(16) uint32_t g_ks [(size_t)MTOK * EMBD / 2]; // K bf16 small
__device__ __align__(16) float    g_vt [(size_t)MTOK * EMBD];     // V tf32

// ---------------------------------------------------------------------------
// Helpers
// ---------------------------------------------------------------------------
__device__ __forceinline__ float f2tf(float x) {
    uint32_t u;
    asm("cvt.rna.tf32.f32 %0, %1;" : "=r"(u) : "f"(x));
    return __uint_as_float(u);
}
__device__ __forceinline__ float bfr(float x) {
    return __bfloat162float(__float2bfloat16_rn(x));
}
__device__ __forceinline__ uint32_t pack_bf(float lo, float hi) {
    __nv_bfloat162 h = __floats2bfloat162_rn(lo, hi);
    return *reinterpret_cast<uint32_t*>(&h);
}

__device__ __forceinline__ void mma_tf32(float c[4], const uint32_t a[4],
                                         const uint32_t b[2]) {
    asm volatile(
        "mma.sync.aligned.m16n8k8.row.col.f32.tf32.tf32.f32 "
        "{%0,%1,%2,%3}, {%4,%5,%6,%7}, {%8,%9}, {%0,%1,%2,%3};"
        : "+f"(c[0]), "+f"(c[1]), "+f"(c[2]), "+f"(c[3])
        : "r"(a[0]), "r"(a[1]), "r"(a[2]), "r"(a[3]), "r"(b[0]), "r"(b[1]));
}
__device__ __forceinline__ void mma_bf16(float c[4], const uint32_t a[4],
                                         const uint32_t b[2]) {
    asm volatile(
        "mma.sync.aligned.m16n8k16.row.col.f32.bf16.bf16.f32 "
        "{%0,%1,%2,%3}, {%4,%5,%6,%7}, {%8,%9}, {%0,%1,%2,%3};"
        : "+f"(c[0]), "+f"(c[1]), "+f"(c[2]), "+f"(c[3])
        : "r"(a[0]), "r"(a[1]), "r"(a[2]), "r"(a[3]), "r"(b[0]), "r"(b[1]));
}

__device__ __forceinline__ void cp_async16p(void* dst_smem, const void* src) {
    uint32_t sa = (uint32_t)__cvta_generic_to_shared(dst_smem);
    asm volatile("cp.async.cg.shared.global [%0], [%1], 16;\n"
                 :: "r"(sa), "l"(src));
}
__device__ __forceinline__ void cp_commit() {
    asm volatile("cp.async.commit_group;\n");
}
template<int N>
__device__ __forceinline__ void cp_wait() {
    asm volatile("cp.async.wait_group %0;\n" :: "n"(N));
}

// ---------------------------------------------------------------------------
// Prep kernels: emit fragment-major, tf32-rounded operands.
// NOTE: destinations are __device__ symbols referenced in DEVICE code only —
// passing them as host-side kernel args resolves to the host shadow symbol
// (silently writable via ATS on GB300) and was the round-7/8 correctness bug.
// ---------------------------------------------------------------------------
__global__ __launch_bounds__(256) void prep_a_kernel(
    const float* __restrict__ src)
{
    size_t id = (size_t)blockIdx.x * 256 + threadIdx.x;  // (tile, lane)
    size_t tile = id >> 5;
    int lane = (int)(id & 31);
    int mt = (int)(tile >> 7), kt = (int)(tile & 127);
    int g = lane >> 2, tg = lane & 3;
    const float* s = src + (size_t)(mt * 16 + g) * EMBD + kt * 8 + tg;
    float v0 = s[0];
    float v1 = s[8 * EMBD];
    float v2 = s[4];
    float v3 = s[8 * EMBD + 4];
    *reinterpret_cast<float4*>(g_xf + id * 4) =
        make_float4(f2tf(v0), f2tf(v1), f2tf(v2), f2tf(v3));
}

__device__ __forceinline__ void prep_b_body(
    const float* __restrict__ w, float* __restrict__ dst, int N)
{
    size_t id = (size_t)blockIdx.x * 256 + threadIdx.x;
    size_t tile = id >> 5;
    int lane = (int)(id & 31);
    int nt = (int)(tile >> 7), kt = (int)(tile & 127);
    int g = lane >> 2, tg = lane & 3;
    int n = nt * 8 + g, k = kt * 8 + tg;
    float v0 = w[(size_t)k * N + n];
    float v1 = w[(size_t)(k + 4) * N + n];
    *reinterpret_cast<float2*>(dst + id * 2) = make_float2(f2tf(v0), f2tf(v1));
}

__global__ __launch_bounds__(256) void prep_b_attn_kernel(
    const float* __restrict__ w)
{
    prep_b_body(w, g_wfa, QKV3);
}

__global__ __launch_bounds__(256) void prep_b_proj_kernel(
    const float* __restrict__ w)
{
    prep_b_body(w, g_wfp, EMBD);
}

// ---------------------------------------------------------------------------
// TF32 GEMM, fragment-major operands, BK=32, 3-stage cp.async pipeline.
// CTA tile 128x128, 256 threads (8 warps: 4(m) x 2(n)), warp 32x64.
// mode 0: out[row][col] (proj).  mode 1: qkv epilogue (Q/K-split/V).
// ---------------------------------------------------------------------------
#define STG_A 4096                 // floats per A stage (8 mt x 4 kt x 128)
#define STG_B 4096                 // floats per B stage (16 nt x 4 kt x 64)
#define STG_FLOATS (STG_A + STG_B)
#define GEMM_SMEM_BYTES (3 * STG_FLOATS * 4)   // 98304

__device__ __forceinline__ void gemm_body(
    const float* __restrict__ Af, const float* __restrict__ Bf,
    const float* __restrict__ bias, float* __restrict__ C, int mode)
{
    extern __shared__ float gsm[];

    const int tid = threadIdx.x, wid = tid >> 5, lane = tid & 31;
    const int g = lane >> 2, tg = lane & 3;
    const int wm = wid & 3, wn = wid >> 2;
    const int row0 = blockIdx.y * 128, col0 = blockIdx.x * 128;
    const int mt0 = blockIdx.y * 8, nt0 = blockIdx.x * 16;

    float c[2][8][4];
#pragma unroll
    for (int mf = 0; mf < 2; mf++)
#pragma unroll
        for (int nf = 0; nf < 8; nf++)
#pragma unroll
            for (int i = 0; i < 4; i++) c[mf][nf][i] = 0.f;

    // fill one 32-K stage: A 1024 chunks, B 1024 chunks (16B each)
    auto fill = [&](int kb, int st) {
        float* as = gsm + st * STG_FLOATS;
        float* bs = as + STG_A;
#pragma unroll
        for (int l = 0; l < 4; l++) {
            int ch = tid + l * 256;
            int mtl = ch >> 7, off = (ch & 127) * 4;
            cp_async16p(&as[mtl * 512 + off],
                        &Af[((size_t)(mt0 + mtl) * KD8 + kb * 4) * 128 + off]);
        }
#pragma unroll
        for (int l = 0; l < 4; l++) {
            int ch = tid + l * 256;
            int ntl = ch >> 6, off = (ch & 63) * 4;
            cp_async16p(&bs[ntl * 256 + off],
                        &Bf[((size_t)(nt0 + ntl) * KD8 + kb * 4) * 64 + off]);
        }
        cp_commit();
    };

    const int nk = 32;   // K=1024 / BK=32
    fill(0, 0);
    fill(1, 1);

    for (int it = 0; it < nk; it++) {
        if (it + 1 < nk) cp_wait<1>(); else cp_wait<0>();
        __syncthreads();

        const float* as = gsm + (it % 3) * STG_FLOATS;
        const float* bs = as + STG_A;

#pragma unroll
        for (int ktl = 0; ktl < 4; ktl++) {
            uint32_t a[2][4], b[8][2];
#pragma unroll
            for (int mf = 0; mf < 2; mf++) {
                float4 av = *reinterpret_cast<const float4*>(
                    &as[((wm * 2 + mf) * 4 + ktl) * 128 + lane * 4]);
                a[mf][0] = __float_as_uint(av.x);
                a[mf][1] = __float_as_uint(av.y);
                a[mf][2] = __float_as_uint(av.z);
                a[mf][3] = __float_as_uint(av.w);
            }
#pragma unroll
            for (int nf = 0; nf < 8; nf++) {
                float2 bv = *reinterpret_cast<const float2*>(
                    &bs[((wn * 8 + nf) * 4 + ktl) * 64 + lane * 2]);
                b[nf][0] = __float_as_uint(bv.x);
                b[nf][1] = __float_as_uint(bv.y);
            }
#pragma unroll
            for (int mf = 0; mf < 2; mf++)
#pragma unroll
                for (int nf = 0; nf < 8; nf++)
                    mma_tf32(c[mf][nf], a[mf], b[nf]);
        }

        if (it + 2 < nk) fill(it + 2, (it + 2) % 3);
    }

    const int region = col0 >> 10;   // mode 1: 0=Q, 1=K, 2=V

#pragma unroll
    for (int mf = 0; mf < 2; mf++) {
        int r_lo = row0 + wm * 32 + mf * 16 + g;
#pragma unroll
        for (int nf = 0; nf < 8; nf++) {
            int cc = col0 + wn * 64 + nf * 8 + tg * 2;
            float b0 = bias[cc], b1 = bias[cc + 1];
            float v00 = c[mf][nf][0] + b0, v01 = c[mf][nf][1] + b1;
            float v10 = c[mf][nf][2] + b0, v11 = c[mf][nf][3] + b1;
            if (mode == 0) {
                *reinterpret_cast<float2*>(&C[(size_t)r_lo * EMBD + cc]) =
                    make_float2(v00, v01);
                *reinterpret_cast<float2*>(&C[(size_t)(r_lo + 8) * EMBD + cc]) =
                    make_float2(v10, v11);
            } else if (region == 0) {
                *reinterpret_cast<float2*>(&g_q[(size_t)r_lo * EMBD + cc]) =
                    make_float2(v00, v01);
                *reinterpret_cast<float2*>(&g_q[(size_t)(r_lo + 8) * EMBD + cc]) =
                    make_float2(v10, v11);
            } else if (region == 1) {
                int col = cc - EMBD;
                float h00 = bfr(v00), h01 = bfr(v01);
                float h10 = bfr(v10), h11 = bfr(v11);
                size_t w0 = ((size_t)r_lo * EMBD + col) >> 1;
                size_t w1 = ((size_t)(r_lo + 8) * EMBD + col) >> 1;
                g_kb[w0] = pack_bf(h00, h01);
                g_ks[w0] = pack_bf(v00 - h00, v01 - h01);
                g_kb[w1] = pack_bf(h10, h11);
                g_ks[w1] = pack_bf(v10 - h10, v11 - h11);
            } else {
                int col = cc - 2 * EMBD;
                *reinterpret_cast<float2*>(&g_vt[(size_t)r_lo * EMBD + col]) =
                    make_float2(f2tf(v00), f2tf(v01));
                *reinterpret_cast<float2*>(&g_vt[(size_t)(r_lo + 8) * EMBD + col]) =
                    make_float2(f2tf(v10), f2tf(v11));
            }
        }
    }
}

__global__ __launch_bounds__(256, 2) void qkv_gemm_kernel(
    const float* __restrict__ bias)
{
    gemm_body(g_xf, g_wfa, bias, nullptr, 1);
}

__global__ __launch_bounds__(256, 2) void proj_gemm_kernel(
    const float* __restrict__ bias, float* __restrict__ out)
{
    gemm_body(g_af, g_wfp, bias, out, 0);
}

// ---------------------------------------------------------------------------
// Tensor-core flash attention (causal) — epilogue writes the proj A-operand
// directly in A-frag layout (tf32-rounded).
// ---------------------------------------------------------------------------
#define QKW 36
#define AVS 72
#define APS 68
#define QBW (64 * QKW)
#define STAGE_W (QBW + QBW + 64 * AVS)
#define OFF_ST0 (2 * QBW)
#define OFF_P   (OFF_ST0 + 2 * STAGE_W)
#define ATT_SMEM_BYTES ((OFF_P + 4 * 16 * APS) * 4)

__device__ __forceinline__ void st_afrag(float v, int r, int c) {
    size_t idx = ((size_t)(r >> 4) * KD8 + (c >> 3)) * 128
               + ((r & 7) * 4 + (c & 3)) * 4
               + ((r >> 3) & 1) + 2 * ((c >> 2) & 1);
    g_af[idx] = f2tf(v);
}

__global__ __launch_bounds__(128) void flash_attn_kernel()
{
    extern __shared__ uint32_t smw[];
    uint32_t* qb = smw;
    uint32_t* qs = smw + QBW;

    const int tid = threadIdx.x, lane = tid & 31, w = tid >> 5;
    const int g = lane >> 2, tg = lane & 3;
    const int qt = blockIdx.x, h = blockIdx.y, b = blockIdx.z;
    float* ps = reinterpret_cast<float*>(smw + OFF_P) + w * 16 * APS;

    const int bsq = b * SEQ;
    const float scale = 0.125f;

    auto issue_kv = [&](int kt, int st) {
        uint32_t* kbs = smw + OFF_ST0 + st * STAGE_W;
        uint32_t* kss = kbs + QBW;
        float* vss = reinterpret_cast<float*>(kss + QBW);
#pragma unroll
        for (int l = 0; l < 4; l++) {
            int id = tid + l * 128;
            int r = id >> 3, ch = id & 7;
            cp_async16p(&kbs[r * QKW + ch * 4],
                        &g_kb[(size_t)(bsq + kt * 64 + r) * 512 + h * 32 + ch * 4]);
        }
#pragma unroll
        for (int l = 0; l < 4; l++) {
            int id = tid + l * 128;
            int r = id >> 3, ch = id & 7;
            cp_async16p(&kss[r * QKW + ch * 4],
                        &g_ks[(size_t)(bsq + kt * 64 + r) * 512 + h * 32 + ch * 4]);
        }
#pragma unroll
        for (int l = 0; l < 8; l++) {
            int id = tid + l * 128;
            int r = id >> 4, ch = id & 15;
            cp_async16p(&vss[r * AVS + ch * 4],
                        &g_vt[(size_t)(bsq + kt * 64 + r) * EMBD + h * HDIM + ch * 4]);
        }
        cp_commit();
    };

    issue_kv(0, 0);

#pragma unroll
    for (int l = 0; l < 8; l++) {
        int id = tid + l * 128;
        int r = id >> 4, c = (id & 15) * 4;
        float4 v = *reinterpret_cast<const float4*>(
            &g_q[(size_t)(bsq + qt * 64 + r) * EMBD + h * HDIM + c]);
        v.x *= scale; v.y *= scale; v.z *= scale; v.w *= scale;
        float bx = bfr(v.x), by = bfr(v.y), bz = bfr(v.z), bw = bfr(v.w);
        *reinterpret_cast<uint2*>(&qb[r * QKW + (c >> 1)]) =
            make_uint2(pack_bf(bx, by), pack_bf(bz, bw));
        *reinterpret_cast<uint2*>(&qs[r * QKW + (c >> 1)]) =
            make_uint2(pack_bf(v.x - bx, v.y - by), pack_bf(v.z - bz, v.w - bw));
    }

    float m0 = -CUDART_INF_F, m1 = -CUDART_INF_F;
    float l0 = 0.f, l1 = 0.f;
    float o[8][4];
#pragma unroll
    for (int nf = 0; nf < 8; nf++)
#pragma unroll
        for (int i = 0; i < 4; i++) o[nf][i] = 0.f;

    const int row_g = qt * 64 + w * 16 + g;
    const int nkt = qt + 1;

    for (int kt = 0; kt < nkt; kt++) {
        if (kt + 1 < nkt) { issue_kv(kt + 1, (kt + 1) & 1); cp_wait<1>(); }
        else cp_wait<0>();
        __syncthreads();

        const int st = kt & 1;
        const uint32_t* kbs = smw + OFF_ST0 + st * STAGE_W;
        const uint32_t* kss = kbs + QBW;
        const float* vss = reinterpret_cast<const float*>(kss + QBW);

        float s[8][4];
#pragma unroll
        for (int nf = 0; nf < 8; nf++)
#pragma unroll
            for (int i = 0; i < 4; i++) s[nf][i] = 0.f;

#pragma unroll
        for (int kc = 0; kc < 4; kc++) {
            const int d0w = kc * 8;
            const int r0 = w * 16 + g;
            uint32_t ab[4], as2[4];
            ab[0] = qb[r0 * QKW + d0w + tg];
            ab[1] = qb[(r0 + 8) * QKW + d0w + tg];
            ab[2] = qb[r0 * QKW + d0w + tg + 4];
            ab[3] = qb[(r0 + 8) * QKW + d0w + tg + 4];
            as2[0] = qs[r0 * QKW + d0w + tg];
            as2[1] = qs[(r0 + 8) * QKW + d0w + tg];
            as2[2] = qs[r0 * QKW + d0w + tg + 4];
            as2[3] = qs[(r0 + 8) * QKW + d0w + tg + 4];
#pragma unroll
            for (int nf = 0; nf < 8; nf++) {
                const int t0 = nf * 8;
                uint32_t bb[2], bs[2];
                bb[0] = kbs[(t0 + g) * QKW + d0w + tg];
                bb[1] = kbs[(t0 + g) * QKW + d0w + tg + 4];
                bs[0] = kss[(t0 + g) * QKW + d0w + tg];
                bs[1] = kss[(t0 + g) * QKW + d0w + tg + 4];
                mma_bf16(s[nf], ab, bb);
                mma_bf16(s[nf], as2, bb);
                mma_bf16(s[nf], ab, bs);
            }
        }

        if (kt == qt) {
#pragma unroll
            for (int nf = 0; nf < 8; nf++) {
                int cbase = kt * 64 + nf * 8 + 2 * tg;
                if (cbase > row_g)         s[nf][0] = -CUDART_INF_F;
                if (cbase + 1 > row_g)     s[nf][1] = -CUDART_INF_F;
                if (cbase > row_g + 8)     s[nf][2] = -CUDART_INF_F;
                if (cbase + 1 > row_g + 8) s[nf][3] = -CUDART_INF_F;
            }
        }

        float t0m = -CUDART_INF_F, t1m = -CUDART_INF_F;
#pragma unroll
        for (int nf = 0; nf < 8; nf++) {
            t0m = fmaxf(t0m, fmaxf(s[nf][0], s[nf][1]));
            t1m = fmaxf(t1m, fmaxf(s[nf][2], s[nf][3]));
        }
        t0m = fmaxf(t0m, __shfl_xor_sync(0xffffffffu, t0m, 1));
        t0m = fmaxf(t0m, __shfl_xor_sync(0xffffffffu, t0m, 2));
        t1m = fmaxf(t1m, __shfl_xor_sync(0xffffffffu, t1m, 1));
        t1m = fmaxf(t1m, __shfl_xor_sync(0xffffffffu, t1m, 2));

        float mn0 = fmaxf(m0, t0m), mn1 = fmaxf(m1, t1m);
        float c0 = __expf(m0 - mn0), c1 = __expf(m1 - mn1);

        float psum0 = 0.f, psum1 = 0.f;
#pragma unroll
        for (int nf = 0; nf < 8; nf++) {
            float p00 = f2tf(__expf(s[nf][0] - mn0));
            float p01 = f2tf(__expf(s[nf][1] - mn0));
            float p10 = f2tf(__expf(s[nf][2] - mn1));
            float p11 = f2tf(__expf(s[nf][3] - mn1));
            psum0 += p00 + p01;
            psum1 += p10 + p11;
            int cc = nf * 8 + 2 * tg;
            ps[g * APS + cc] = p00;       ps[g * APS + cc + 1] = p01;
            ps[(g + 8) * APS + cc] = p10; ps[(g + 8) * APS + cc + 1] = p11;
        }
        psum0 += __shfl_xor_sync(0xffffffffu, psum0, 1);
        psum0 += __shfl_xor_sync(0xffffffffu, psum0, 2);
        psum1 += __shfl_xor_sync(0xffffffffu, psum1, 1);
        psum1 += __shfl_xor_sync(0xffffffffu, psum1, 2);

        l0 = l0 * c0 + psum0;
        l1 = l1 * c1 + psum1;
        m0 = mn0; m1 = mn1;

#pragma unroll
        for (int nf = 0; nf < 8; nf++) {
            o[nf][0] *= c0; o[nf][1] *= c0;
            o[nf][2] *= c1; o[nf][3] *= c1;
        }

        __syncwarp();

#pragma unroll
        for (int kc = 0; kc < 8; kc++) {
            const int t0 = kc * 8;
            uint32_t a[4];
            a[0] = __float_as_uint(ps[g * APS + t0 + tg]);
            a[1] = __float_as_uint(ps[(g + 8) * APS + t0 + tg]);
            a[2] = __float_as_uint(ps[g * APS + t0 + tg + 4]);
            a[3] = __float_as_uint(ps[(g + 8) * APS + t0 + tg + 4]);
#pragma unroll
            for (int nf = 0; nf < 8; nf++) {
                const int d0 = nf * 8;
                uint32_t bv[2];
                bv[0] = __float_as_uint(vss[(t0 + tg) * AVS + d0 + g]);
                bv[1] = __float_as_uint(vss[(t0 + tg + 4) * AVS + d0 + g]);
                mma_tf32(o[nf], a, bv);
            }
        }
        __syncthreads();
    }

    // Epilogue: normalize + write proj A-operand in fragment layout
    float inv0 = 1.f / l0, inv1 = 1.f / l1;
    const int gr0 = bsq + row_g;          // global token rows
#pragma unroll
    for (int nf = 0; nf < 8; nf++) {
        int c0c = h * HDIM + nf * 8 + 2 * tg;
        st_afrag(o[nf][0] * inv0, gr0,     c0c);
        st_afrag(o[nf][1] * inv0, gr0,     c0c + 1);
        st_afrag(o[nf][2] * inv1, gr0 + 8, c0c);
        st_afrag(o[nf][3] * inv1, gr0 + 8, c0c + 1);
    }
}

// ---------------------------------------------------------------------------
// Launch
// ---------------------------------------------------------------------------
extern "C" void kernel_launch(void* const* d_in, const int* in_sizes, int n_in,
                              void* d_out, int out_size)
{
    const float* x      = (const float*)d_in[0];
    const float* w_attn = (const float*)d_in[1];
    const float* b_attn = (const float*)d_in[2];
    const float* w_proj = (const float*)d_in[3];
    const float* b_proj = (const float*)d_in[4];
    float* out = (float*)d_out;

    cudaFuncSetAttribute(qkv_gemm_kernel,
                         cudaFuncAttributeMaxDynamicSharedMemorySize,
                         GEMM_SMEM_BYTES);
    cudaFuncSetAttribute(proj_gemm_kernel,
                         cudaFuncAttributeMaxDynamicSharedMemorySize,
                         GEMM_SMEM_BYTES);
    cudaFuncSetAttribute(flash_attn_kernel,
                         cudaFuncAttributeMaxDynamicSharedMemorySize,
                         ATT_SMEM_BYTES);

    // Prep: x -> A-frag, W^T -> B-frag (tf32-rounded once)
    prep_a_kernel<<<(unsigned)(((size_t)(MTOK / 16) * KD8 * 32) / 256), 256>>>(x);
    prep_b_attn_kernel<<<(unsigned)(((size_t)(QKV3 / 8) * KD8 * 32) / 256), 256>>>(
        w_attn);
    prep_b_proj_kernel<<<(unsigned)(((size_t)(EMBD / 8) * KD8 * 32) / 256), 256>>>(
        w_proj);

    // QKV GEMM -> Q/K/V attention buffers
    qkv_gemm_kernel<<<dim3(QKV3 / 128, MTOK / 128), 256, GEMM_SMEM_BYTES>>>(
        b_attn);

    // Flash attention -> proj A-operand (frag layout)
    flash_attn_kernel<<<dim3(SEQ / 64, NHEAD, BATCH), 128, ATT_SMEM_BYTES>>>();

    // Proj GEMM -> out
    proj_gemm_kernel<<<dim3(EMBD / 128, MTOK / 128), 256, GEMM_SMEM_BYTES>>>(
        b_proj, out);
}